// round 13
// baseline (speedup 1.0000x reference)
#include <cuda_runtime.h>

#define NB 64
#define NEe 8978
#define NE2e 4489
#define NN1 (NB*NEe)
#define NN2 (NB*NE2e)
#define NEDGE1 (NN1*16)
#define NEDGE2 (NN2*16)
#define SLOPEc 0.33f
#define GSB 1184
#define MCHK 562
#define YSZ ((size_t)NN2*32)

__device__ float g_s1[NN1], g_s2[NN1], g_s3[NN1];
__device__ float g_Y[4*NN2*32];
__device__ float g_R1[NN2*32], g_R2[NN2*32], g_O1[NN2*32];
__device__ float g_w0[NN2], g_w1[NN2], g_w2[NN2], g_w3[NN2];
__device__ float g_raw2[NN2];
__device__ float g_A[4096], g_a0[128], g_aV[128];
__device__ double g_st0[14*16], g_sum1[32*16], g_sq1[32*16], g_st2[2*16];
__device__ float g_scale0[32], g_shift0[32], g_scale1[32], g_shift1[32], g_bn2s[2];
__device__ float g_h1raw[64*256], g_h1[64*256], g_h2raw[64*128];
__device__ unsigned short g_u16a[NEDGE1], g_u16b[NEDGE2];

__constant__ float c_C[16] = {1.f,0.f,0.f,0.f, 1.f,-1.f,0.f,0.f,
                              1.f,-2.f,0.5f,0.f, 1.f,-3.f,1.5f,-0.16666666666666666f};

__device__ __forceinline__ float leaky(float v){ return v>0.f? v : SLOPEc*v; }

__global__ void k_prep(const float* __restrict__ W0, const float* __restrict__ W1,
                       const float* __restrict__ W2, const int* __restrict__ src1,
                       const int* __restrict__ src2){
    int t = blockIdx.x*blockDim.x + threadIdx.x, stride = gridDim.x*blockDim.x;
    for (int i=t;i<NEDGE1;i+=stride)
        g_u16a[i]=(unsigned short)(src1[i]-(i/(NEe*16))*NEe);
    for (int i=t;i<NEDGE2;i+=stride)
        g_u16b[i]=(unsigned short)(src2[i]-(i/(NE2e*16))*NE2e);
    for (int idx=t; idx<4096; idx+=stride){
        int m = idx>>10, ic = idx&1023;
        float s=0.f;
        #pragma unroll
        for (int k=0;k<4;k++) s = fmaf(c_C[k*4+m], W1[k*1024+ic], s);
        g_A[idx]=s;
    }
    for (int idx=t; idx<128; idx+=stride){
        int m = idx>>5, c = idx&31;
        float s0=0.f, sv=0.f;
        #pragma unroll
        for (int k=0;k<4;k++){
            float cc = c_C[k*4+m];
            s0 = fmaf(cc, W0[k*32+c], s0);
            sv = fmaf(cc, W2[k*32+c], sv);
        }
        g_a0[idx]=s0; g_aV[idx]=sv;
    }
    for (int idx=t; idx<14*16; idx+=stride) g_st0[idx]=0.0;
    for (int idx=t; idx<32*16; idx+=stride){ g_sum1[idx]=0.0; g_sq1[idx]=0.0; }
    for (int idx=t; idx<2*16;  idx+=stride) g_st2[idx]=0.0;
    for (int idx=t; idx<64*256; idx+=stride) g_h1raw[idx]=0.f;
}

__device__ __forceinline__ float gth16(const float* __restrict__ sbuf,
        const unsigned short* __restrict__ s16, const float* __restrict__ w, int n){
    float acc=0.f;
    const ushort4* sp = reinterpret_cast<const ushort4*>(s16) + n*4;
    const float4*  wp = reinterpret_cast<const float4*>(w) + n*4;
    #pragma unroll
    for (int q=0;q<4;q++){
        ushort4 s = sp[q]; float4 ww = __ldg(wp+q);
        acc = fmaf(ww.x, sbuf[s.x], acc);
        acc = fmaf(ww.y, sbuf[s.y], acc);
        acc = fmaf(ww.z, sbuf[s.z], acc);
        acc = fmaf(ww.w, sbuf[s.w], acc);
    }
    return acc;
}

// ---- layer 0 fused: stage once, s1->s2->s3+stats, block per graph ----
__global__ void __launch_bounds__(1024) k_l0chain(const float* __restrict__ x,
                                                  const float* __restrict__ ew){
    extern __shared__ float sm[];
    float* A = sm; float* B = sm + NEe;
    __shared__ float shst[14];
    int g = blockIdx.x, tid = threadIdx.x;
    long nb = (long)g*NEe;
    const unsigned short* s16 = g_u16a + nb*16;
    const float* w = ew + nb*16;
    if (tid<14) shst[tid]=0.f;
    for (int n=tid;n<NEe;n+=1024) A[n] = __ldg(x+nb+n);
    __syncthreads();
    for (int n=tid;n<NEe;n+=1024){ float a=gth16(A,s16,w,n); B[n]=a; g_s1[nb+n]=a; }
    __syncthreads();
    for (int n=tid;n<NEe;n+=1024){ float a=gth16(B,s16,w,n); A[n]=a; g_s2[nb+n]=a; }
    __syncthreads();
    float st[14];
    #pragma unroll
    for (int j=0;j<14;j++) st[j]=0.f;
    for (int n=tid;n<NEe;n+=1024){
        float a = gth16(A,s16,w,n);
        g_s3[nb+n]=a;
        float v0=__ldg(x+nb+n), v1=B[n], v2=A[n], v3=a;
        st[0]+=v0; st[1]+=v1; st[2]+=v2; st[3]+=v3;
        st[4]+=v0*v0; st[5]+=v0*v1; st[6]+=v0*v2; st[7]+=v0*v3;
        st[8]+=v1*v1; st[9]+=v1*v2; st[10]+=v1*v3;
        st[11]+=v2*v2; st[12]+=v2*v3; st[13]+=v3*v3;
    }
    #pragma unroll
    for (int j=0;j<14;j++){
        #pragma unroll
        for (int r=16;r;r>>=1) st[j] += __shfl_xor_sync(0xffffffffu, st[j], r);
    }
    if ((tid&31)==0){
        #pragma unroll
        for (int j=0;j<14;j++) atomicAdd(&shst[j], st[j]);
    }
    __syncthreads();
    if (tid<14) atomicAdd(&g_st0[tid*16 + (g&15)], (double)shst[tid]);
}

__global__ void k_fin0(const float* __restrict__ b0, const float* __restrict__ g0,
                       const float* __restrict__ be0){
    int c = threadIdx.x; if (c>=32) return;
    double st[14];
    for (int j=0;j<14;j++){ double s=0; for (int q=0;q<16;q++) s+=g_st0[j*16+q]; st[j]=s; }
    double invN = 1.0/(double)NN1, mu[4];
    for (int m=0;m<4;m++) mu[m]=st[m]*invN;
    double cov[4][4]; int idx=4;
    for (int m=0;m<4;m++) for (int mm=m;mm<4;mm++){
        double cc = st[idx]*invN - mu[m]*mu[mm];
        cov[m][mm]=cc; cov[mm][m]=cc; idx++;
    }
    double a[4];
    for (int m=0;m<4;m++) a[m]=(double)g_a0[m*32+c];
    double proj=0, var=0;
    for (int m=0;m<4;m++) proj += mu[m]*a[m];
    for (int m=0;m<4;m++) for (int mm=0;mm<4;mm++) var += a[m]*a[mm]*cov[m][mm];
    double sc = (double)g0[c]/sqrt(var+1e-5);
    g_scale0[c]=(float)sc;
    g_shift0[c]=(float)((double)be0[c] - proj*sc);
}

// ---- pool + BN + mix as tiled GEMM ----
__global__ void __launch_bounds__(256) k_poolmix(const float* __restrict__ x){
    __shared__ float Xs[32*68];
    __shared__ float As[32*128];
    int tid=threadIdx.x, lane=tid&31, wid=tid>>5;
    for (int idx=tid; idx<4096; idx+=256){
        int k=idx>>7, col=idx&127, m=col>>5, c=col&31;
        As[idx] = g_A[m*1024 + k*32 + c];
    }
    float a0=g_a0[lane], a1=g_a0[32+lane], a2=g_a0[64+lane], a3=g_a0[96+lane];
    float sc=g_scale0[lane], sf=g_shift0[lane];
    int nbase = blockIdx.x*64;
    #pragma unroll
    for (int j=0;j<8;j++){
        int nl = wid*8+j, n = nbase+nl;
        int b = n/NE2e, e2 = n-b*NE2e; int m0 = b*NEe + 2*e2;
        float s0a=__ldg(x+m0),   s1a=g_s1[m0],   s2a=g_s2[m0],   s3a=g_s3[m0];
        float s0b=__ldg(x+m0+1), s1b=g_s1[m0+1], s2b=g_s2[m0+1], s3b=g_s3[m0+1];
        float ra = fmaf(s0a,a0, fmaf(s1a,a1, fmaf(s2a,a2, s3a*a3)));
        float rb = fmaf(s0b,a0, fmaf(s1b,a1, fmaf(s2b,a2, s3b*a3)));
        Xs[lane*68 + nl] = fmaxf(leaky(fmaf(ra,sc,sf)), leaky(fmaf(rb,sc,sf)));
    }
    __syncthreads();
    int tr = tid&15, tcg = tid>>4;
    float acc[4][8];
    #pragma unroll
    for (int r=0;r<4;r++)
        #pragma unroll
        for (int c=0;c<8;c++) acc[r][c]=0.f;
    #pragma unroll 4
    for (int k=0;k<32;k++){
        float4 xr = *reinterpret_cast<float4*>(&Xs[k*68 + 4*tr]);
        float4 av0 = *reinterpret_cast<float4*>(&As[k*128 + 8*tcg]);
        float4 av1 = *reinterpret_cast<float4*>(&As[k*128 + 8*tcg + 4]);
        float xv[4] = {xr.x, xr.y, xr.z, xr.w};
        float av[8] = {av0.x,av0.y,av0.z,av0.w, av1.x,av1.y,av1.z,av1.w};
        #pragma unroll
        for (int r=0;r<4;r++)
            #pragma unroll
            for (int c=0;c<8;c++) acc[r][c] = fmaf(xv[r], av[c], acc[r][c]);
    }
    int m = tcg>>2, cc = (tcg&3)*8;
    float* Yp = g_Y + (size_t)m*YSZ;
    #pragma unroll
    for (int r=0;r<4;r++){
        size_t base = (size_t)(nbase + 4*tr + r)*32 + cc;
        *reinterpret_cast<float4*>(&Yp[base])   = make_float4(acc[r][0],acc[r][1],acc[r][2],acc[r][3]);
        *reinterpret_cast<float4*>(&Yp[base+4]) = make_float4(acc[r][4],acc[r][5],acc[r][6],acc[r][7]);
    }
}

// ---- 32-ch matvec: 4 nodes per warp ----
__global__ void __launch_bounds__(256) k_mvA(const int* __restrict__ src,
                                             const float* __restrict__ ew){
    __shared__ int ss[8][64]; __shared__ float sw[8][64];
    int tid=threadIdx.x, lane=tid&31, wid=tid>>5;
    int n0 = blockIdx.x*32 + wid*4;
    ss[wid][lane]=src[n0*16+lane];    ss[wid][32+lane]=src[n0*16+32+lane];
    sw[wid][lane]=ew[n0*16+lane];     sw[wid][32+lane]=ew[n0*16+32+lane];
    __syncwarp();
    const float* v = g_Y + 3*YSZ;
    float acc0 = g_Y[2*YSZ + (size_t)n0*32+lane];
    float acc1 = g_Y[2*YSZ + (size_t)(n0+1)*32+lane];
    float acc2 = g_Y[2*YSZ + (size_t)(n0+2)*32+lane];
    float acc3 = g_Y[2*YSZ + (size_t)(n0+3)*32+lane];
    #pragma unroll
    for (int j=0;j<16;j++){
        acc0 = fmaf(sw[wid][j],    __ldg(v + (size_t)ss[wid][j]*32 + lane), acc0);
        acc1 = fmaf(sw[wid][16+j], __ldg(v + (size_t)ss[wid][16+j]*32 + lane), acc1);
        acc2 = fmaf(sw[wid][32+j], __ldg(v + (size_t)ss[wid][32+j]*32 + lane), acc2);
        acc3 = fmaf(sw[wid][48+j], __ldg(v + (size_t)ss[wid][48+j]*32 + lane), acc3);
    }
    g_R1[(size_t)n0*32+lane]=acc0;     g_R1[(size_t)(n0+1)*32+lane]=acc1;
    g_R1[(size_t)(n0+2)*32+lane]=acc2; g_R1[(size_t)(n0+3)*32+lane]=acc3;
}
__global__ void __launch_bounds__(256) k_mvB(const int* __restrict__ src,
                                             const float* __restrict__ ew){
    __shared__ int ss[8][64]; __shared__ float sw[8][64];
    int tid=threadIdx.x, lane=tid&31, wid=tid>>5;
    int n0 = blockIdx.x*32 + wid*4;
    ss[wid][lane]=src[n0*16+lane];    ss[wid][32+lane]=src[n0*16+32+lane];
    sw[wid][lane]=ew[n0*16+lane];     sw[wid][32+lane]=ew[n0*16+32+lane];
    __syncwarp();
    float acc0 = g_Y[YSZ + (size_t)n0*32+lane];
    float acc1 = g_Y[YSZ + (size_t)(n0+1)*32+lane];
    float acc2 = g_Y[YSZ + (size_t)(n0+2)*32+lane];
    float acc3 = g_Y[YSZ + (size_t)(n0+3)*32+lane];
    #pragma unroll
    for (int j=0;j<16;j++){
        acc0 = fmaf(sw[wid][j],    __ldg(g_R1 + (size_t)ss[wid][j]*32 + lane), acc0);
        acc1 = fmaf(sw[wid][16+j], __ldg(g_R1 + (size_t)ss[wid][16+j]*32 + lane), acc1);
        acc2 = fmaf(sw[wid][32+j], __ldg(g_R1 + (size_t)ss[wid][32+j]*32 + lane), acc2);
        acc3 = fmaf(sw[wid][48+j], __ldg(g_R1 + (size_t)ss[wid][48+j]*32 + lane), acc3);
    }
    g_R2[(size_t)n0*32+lane]=acc0;     g_R2[(size_t)(n0+1)*32+lane]=acc1;
    g_R2[(size_t)(n0+2)*32+lane]=acc2; g_R2[(size_t)(n0+3)*32+lane]=acc3;
}

__global__ void __launch_bounds__(256) k_mvC(const int* __restrict__ src,
        const float* __restrict__ ew, const float* __restrict__ b1){
    __shared__ int   ss[8][16];
    __shared__ float sw[8][16];
    __shared__ float sum_s[32], sq_s[32];
    int tid=threadIdx.x, lane=tid&31, wid=tid>>5;
    if (tid<32){ sum_s[tid]=0.f; sq_s[tid]=0.f; }
    __syncthreads();
    float bias = __ldg(b1+lane);
    int w0 = blockIdx.x*8 + wid, nw = gridDim.x*8;
    float ps=0.f, pq=0.f;
    for (int n=w0; n<NN2; n+=nw){
        if (lane<16) ss[wid][lane] = src[n*16+lane];
        else         sw[wid][lane-16] = ew[n*16+lane-16];
        __syncwarp();
        float acc = g_Y[(size_t)n*32+lane] + bias;
        #pragma unroll
        for (int j=0;j<16;j++)
            acc = fmaf(sw[wid][j], __ldg(g_R2 + (size_t)ss[wid][j]*32 + lane), acc);
        g_O1[(size_t)n*32+lane] = acc;
        ps += acc; pq += acc*acc;
        __syncwarp();
    }
    atomicAdd(&sum_s[lane], ps); atomicAdd(&sq_s[lane], pq);
    __syncthreads();
    if (tid<32){
        int slot = blockIdx.x&15;
        atomicAdd(&g_sum1[tid*16+slot], (double)sum_s[tid]);
        atomicAdd(&g_sq1[tid*16+slot],  (double)sq_s[tid]);
    }
}

__global__ void k_fin1(const float* __restrict__ g1, const float* __restrict__ be1){
    int c=threadIdx.x; if (c>=32) return;
    double s=0,q=0;
    for (int slot=0;slot<16;slot++){ s+=g_sum1[c*16+slot]; q+=g_sq1[c*16+slot]; }
    double invN = 1.0/(double)NN2;
    double mean=s*invN, var=q*invN-mean*mean;
    double sc=(double)g1[c]/sqrt(var+1e-5);
    g_scale1[c]=(float)sc; g_shift1[c]=(float)((double)be1[c]-mean*sc);
}

__global__ void k_mix2(){
    int w=(blockIdx.x*blockDim.x+threadIdx.x)>>5; if (w>=NN2) return;
    int lane=threadIdx.x&31;
    float o=g_O1[(size_t)w*32+lane];
    float x2=leaky(fmaf(g_scale1[lane], o, g_shift1[lane]));
    float p0=x2*g_aV[lane],     p1=x2*g_aV[32+lane];
    float p2=x2*g_aV[64+lane],  p3=x2*g_aV[96+lane];
    #pragma unroll
    for (int r=16;r;r>>=1){
        p0+=__shfl_xor_sync(0xffffffffu,p0,r); p1+=__shfl_xor_sync(0xffffffffu,p1,r);
        p2+=__shfl_xor_sync(0xffffffffu,p2,r); p3+=__shfl_xor_sync(0xffffffffu,p3,r);
    }
    if (lane==0){ g_w0[w]=p0; g_w1[w]=p1; g_w2[w]=p2; g_w3[w]=p3; }
}

// ---- layer 2 fused scalar chain: block per graph ----
__global__ void __launch_bounds__(1024) k_l2chain(const float* __restrict__ ew,
                                                  const float* __restrict__ b2){
    __shared__ float A[NE2e], Bf[NE2e];
    __shared__ float sred2[2];
    int g = blockIdx.x, tid = threadIdx.x;
    long nb = (long)g*NE2e;
    const unsigned short* s16 = g_u16b + nb*16;
    const float* w = ew + nb*16;
    if (tid<2) sred2[tid]=0.f;
    for (int n=tid;n<NE2e;n+=1024) A[n] = g_w3[nb+n];
    __syncthreads();
    for (int n=tid;n<NE2e;n+=1024) Bf[n] = g_w2[nb+n] + gth16(A,s16,w,n);
    __syncthreads();
    for (int n=tid;n<NE2e;n+=1024) A[n] = g_w1[nb+n] + gth16(Bf,s16,w,n);
    __syncthreads();
    float bias = __ldg(b2);
    float ps=0.f, pq=0.f;
    for (int n=tid;n<NE2e;n+=1024){
        float a = g_w0[nb+n] + bias + gth16(A,s16,w,n);
        g_raw2[nb+n]=a; ps+=a; pq+=a*a;
    }
    #pragma unroll
    for (int r=16;r;r>>=1){
        ps+=__shfl_xor_sync(0xffffffffu,ps,r); pq+=__shfl_xor_sync(0xffffffffu,pq,r);
    }
    if ((tid&31)==0){ atomicAdd(&sred2[0],ps); atomicAdd(&sred2[1],pq); }
    __syncthreads();
    if (tid<2) atomicAdd(&g_st2[tid*16 + (g&15)], (double)sred2[tid]);
}

__global__ void k_finS(const float* __restrict__ g2, const float* __restrict__ be2){
    if (threadIdx.x!=0) return;
    double s=0,q=0;
    for (int slot=0;slot<16;slot++){ s+=g_st2[slot]; q+=g_st2[16+slot]; }
    double invN=1.0/(double)NN2;
    double mean=s*invN, var=q*invN-mean*mean;
    double sc=(double)g2[0]/sqrt(var+1e-5);
    g_bn2s[0]=(float)sc; g_bn2s[1]=(float)((double)be2[0]-mean*sc);
}

__global__ void __launch_bounds__(256) k_mlp1(const float* __restrict__ W,
                                              const float* __restrict__ bb){
    extern __shared__ float sA[];
    int tid = threadIdx.x;
    int cb = blockIdx.x & 7, kc = blockIdx.x >> 3;
    int k0 = kc*MCHK;
    int klen = NE2e - k0; if (klen > MCHK) klen = MCHK;
    float sc = g_bn2s[0], sf = g_bn2s[1];
    for (int idx=tid; idx<64*klen; idx+=256){
        int r = idx / klen, k = idx - r*klen;
        sA[r*MCHK + k] = leaky(fmaf(g_raw2[(long)r*NE2e + k0 + k], sc, sf));
    }
    __syncthreads();
    int col = cb*32 + (tid&31);
    int r0 = (tid>>5)*8;
    float acc[8];
    #pragma unroll
    for (int r=0;r<8;r++) acc[r]=0.f;
    for (int k=0;k<klen;k++){
        float wv = __ldg(W + (long)(k0+k)*256 + col);
        #pragma unroll
        for (int r=0;r<8;r++) acc[r] = fmaf(sA[(r0+r)*MCHK + k], wv, acc[r]);
    }
    float bias = (kc==0) ? __ldg(bb+col) : 0.f;
    #pragma unroll
    for (int r=0;r<8;r++) atomicAdd(&g_h1raw[(r0+r)*256 + col], acc[r] + bias);
}

__global__ void k_bn1(const float* __restrict__ g, const float* __restrict__ be){
    int c=threadIdx.x;
    float s=0.f,q=0.f;
    #pragma unroll 8
    for (int b=0;b<64;b++){ float v=g_h1raw[b*256+c]; s+=v; q+=v*v; }
    float mean=s*(1.f/64.f), var=q*(1.f/64.f)-mean*mean;
    float sc=__ldg(g+c)*rsqrtf(var+1e-5f), sf=__ldg(be+c)-mean*sc;
    for (int b=0;b<64;b++){
        float v=fmaf(g_h1raw[b*256+c],sc,sf);
        g_h1[b*256+c]= v>0.f? v:0.f;
    }
}

__global__ void k_mlp2(const float* __restrict__ W, const float* __restrict__ bb){
    __shared__ float shx[256];
    int b = blockIdx.x, t = threadIdx.x;
    for (int i=t;i<256;i+=128) shx[i]=g_h1[b*256+i];
    __syncthreads();
    float acc=__ldg(bb+t);
    #pragma unroll 8
    for (int i=0;i<256;i++) acc = fmaf(shx[i], __ldg(W+i*128+t), acc);
    g_h2raw[b*128+t]=acc;
}

__global__ void k_bn2out(const float* __restrict__ g, const float* __restrict__ be,
                         const float* __restrict__ W3, const float* __restrict__ b3,
                         float* __restrict__ out){
    __shared__ float sh2[64*128];
    int c=threadIdx.x;
    float s=0.f,q=0.f;
    #pragma unroll 8
    for (int b=0;b<64;b++){ float v=g_h2raw[b*128+c]; s+=v; q+=v*v; }
    float mean=s*(1.f/64.f), var=q*(1.f/64.f)-mean*mean;
    float sc=__ldg(g+c)*rsqrtf(var+1e-5f), sf=__ldg(be+c)-mean*sc;
    for (int b=0;b<64;b++){
        float v=fmaf(g_h2raw[b*128+c],sc,sf);
        sh2[b*128+c]= v>0.f? v:0.f;
    }
    __syncthreads();
    if (c<64){
        float acc=__ldg(b3);
        #pragma unroll 8
        for (int j=0;j<128;j++) acc=fmaf(sh2[c*128+j], __ldg(W3+j), acc);
        out[c]=acc;
    }
}

extern "C" void kernel_launch(void* const* d_in, const int* in_sizes, int n_in,
                              void* d_out, int out_size){
    const float* x_s  = (const float*)d_in[0];
    const int*   ei1  = (const int*)d_in[1];
    const float* ew1  = (const float*)d_in[2];
    const int*   ei2  = (const int*)d_in[3];
    const float* ew2  = (const float*)d_in[4];
    const float* W0   = (const float*)d_in[5];
    const float* b0   = (const float*)d_in[6];
    const float* g0   = (const float*)d_in[7];
    const float* be0  = (const float*)d_in[8];
    const float* W1   = (const float*)d_in[9];
    const float* b1   = (const float*)d_in[10];
    const float* g1   = (const float*)d_in[11];
    const float* be1  = (const float*)d_in[12];
    const float* W2   = (const float*)d_in[13];
    const float* b2   = (const float*)d_in[14];
    const float* g2   = (const float*)d_in[15];
    const float* be2  = (const float*)d_in[16];
    const float* l1W  = (const float*)d_in[17];
    const float* l1b  = (const float*)d_in[18];
    const float* bn1g = (const float*)d_in[19];
    const float* bn1b = (const float*)d_in[20];
    const float* l2W  = (const float*)d_in[21];
    const float* l2b  = (const float*)d_in[22];
    const float* bn2g = (const float*)d_in[23];
    const float* bn2b = (const float*)d_in[24];
    const float* l3W  = (const float*)d_in[25];
    const float* l3b  = (const float*)d_in[26];
    float* out = (float*)d_out;

    const int smM1 = 64*MCHK*(int)sizeof(float);
    const int smL0 = 2*NEe*(int)sizeof(float);
    static int init = 0;
    if (!init){
        cudaFuncSetAttribute(k_mlp1, cudaFuncAttributeMaxDynamicSharedMemorySize, smM1);
        cudaFuncSetAttribute(k_l0chain, cudaFuncAttributeMaxDynamicSharedMemorySize, smL0);
        init = 1;
    }

    k_prep<<<256,256>>>(W0, W1, W2, ei1, ei2);
    k_l0chain<<<64,1024,smL0>>>(x_s, ew1);
    k_fin0<<<1,32>>>(b0, g0, be0);
    k_poolmix<<<NN2/64,256>>>(x_s);
    k_mvA<<<NN2/32,256>>>(ei2, ew2);
    k_mvB<<<NN2/32,256>>>(ei2, ew2);
    k_mvC<<<GSB,256>>>(ei2, ew2, b1);
    k_fin1<<<1,32>>>(g1, be1);
    k_mix2<<<(NN2*32+255)/256,256>>>();
    k_l2chain<<<64,1024>>>(ew2, b2);
    k_finS<<<1,32>>>(g2, be2);
    k_mlp1<<<64,256,smM1>>>(l1W, l1b);
    k_bn1<<<1,256>>>(bn1g, bn1b);
    k_mlp2<<<64,128>>>(l2W, l2b);
    k_bn2out<<<1,128>>>(bn2g, bn2b, l3W, l3b, out);
}

// round 15
// speedup vs baseline: 1.0492x; 1.0492x over previous
#include <cuda_runtime.h>

#define NB 64
#define NEe 8978
#define NE2e 4489
#define NN1 (NB*NEe)
#define NN2 (NB*NE2e)
#define NEDGE1 (NN1*16)
#define SLOPEc 0.33f
#define GSB 1184
#define MCHK 562
#define CHK0 4489
#define YSZ ((size_t)NN2*32)

__device__ float g_s1[NN1], g_s2[NN1], g_s3[NN1];
__device__ float g_Y[4*NN2*32];
__device__ float g_X1[NN2*32];
__device__ float g_R1[NN2*32], g_R2[NN2*32], g_O1[NN2*32];
__device__ float g_w0[NN2], g_w1[NN2], g_w2[NN2], g_w3[NN2];
__device__ float g_r1[NN2], g_r2[NN2], g_raw2[NN2];
__device__ float g_A[4096], g_a0[128], g_aV[128];
__device__ double g_st0[14*16], g_sum1[32*16], g_sq1[32*16], g_st2[2*16];
__device__ float g_scale0[32], g_shift0[32], g_scale1[32], g_shift1[32], g_bn2s[2];
__device__ float g_h1raw[64*256], g_h1[64*256], g_h2raw[64*128];
__device__ unsigned short g_u16a[NEDGE1];

__constant__ float c_C[16] = {1.f,0.f,0.f,0.f, 1.f,-1.f,0.f,0.f,
                              1.f,-2.f,0.5f,0.f, 1.f,-3.f,1.5f,-0.16666666666666666f};

__device__ __forceinline__ float leaky(float v){ return v>0.f? v : SLOPEc*v; }

__global__ void k_prep(const float* __restrict__ W0, const float* __restrict__ W1,
                       const float* __restrict__ W2, const int* __restrict__ src1){
    int t = blockIdx.x*blockDim.x + threadIdx.x, stride = gridDim.x*blockDim.x;
    for (int i=t;i<NEDGE1;i+=stride)
        g_u16a[i]=(unsigned short)(src1[i]-(i/(NEe*16))*NEe);
    for (int idx=t; idx<4096; idx+=stride){
        int m = idx>>10, ic = idx&1023;
        float s=0.f;
        #pragma unroll
        for (int k=0;k<4;k++) s = fmaf(c_C[k*4+m], W1[k*1024+ic], s);
        g_A[idx]=s;
    }
    for (int idx=t; idx<128; idx+=stride){
        int m = idx>>5, c = idx&31;
        float s0=0.f, sv=0.f;
        #pragma unroll
        for (int k=0;k<4;k++){
            float cc = c_C[k*4+m];
            s0 = fmaf(cc, W0[k*32+c], s0);
            sv = fmaf(cc, W2[k*32+c], sv);
        }
        g_a0[idx]=s0; g_aV[idx]=sv;
    }
    for (int idx=t; idx<14*16; idx+=stride) g_st0[idx]=0.0;
    for (int idx=t; idx<32*16; idx+=stride){ g_sum1[idx]=0.0; g_sq1[idx]=0.0; }
    for (int idx=t; idx<2*16;  idx+=stride) g_st2[idx]=0.0;
    for (int idx=t; idx<64*256; idx+=stride) g_h1raw[idx]=0.f;
}

__device__ __forceinline__ void smv_body(int i, const float* __restrict__ v,
                                         const int* __restrict__ src,
                                         const float* __restrict__ ew, float& acc){
    const int4*   sp = reinterpret_cast<const int4*>(src) + i*4;
    const float4* wp = reinterpret_cast<const float4*>(ew) + i*4;
    #pragma unroll
    for (int q=0;q<4;q++){
        int4 s = __ldg(sp+q); float4 w = __ldg(wp+q);
        acc = fmaf(w.x, __ldg(v+s.x), acc);
        acc = fmaf(w.y, __ldg(v+s.y), acc);
        acc = fmaf(w.z, __ldg(v+s.z), acc);
        acc = fmaf(w.w, __ldg(v+s.w), acc);
    }
}

__device__ __forceinline__ float gth16(const float* __restrict__ sbuf,
        const unsigned short* __restrict__ s16, const float* __restrict__ w, int n){
    float acc=0.f;
    const ushort4* sp = reinterpret_cast<const ushort4*>(s16) + n*4;
    const float4*  wp = reinterpret_cast<const float4*>(w) + n*4;
    #pragma unroll
    for (int q=0;q<4;q++){
        ushort4 s = sp[q]; float4 ww = __ldg(wp+q);
        acc = fmaf(ww.x, sbuf[s.x], acc);
        acc = fmaf(ww.y, sbuf[s.y], acc);
        acc = fmaf(ww.z, sbuf[s.z], acc);
        acc = fmaf(ww.w, sbuf[s.w], acc);
    }
    return acc;
}

// ---- layer 0: 2 chunks per graph, 1024 threads ----
__global__ void __launch_bounds__(1024) k_ls1(const float* __restrict__ x,
                                              const float* __restrict__ ew){
    __shared__ float sX[NEe];
    int g = blockIdx.x>>1, ch = blockIdx.x&1, tid = threadIdx.x;
    long nb = (long)g*NEe;
    for (int n=tid;n<NEe;n+=1024) sX[n] = __ldg(x+nb+n);
    __syncthreads();
    const unsigned short* s16 = g_u16a + nb*16;
    const float* w = ew + nb*16;
    int n1 = ch*CHK0+CHK0; if (n1>NEe) n1=NEe;
    for (int n=ch*CHK0+tid; n<n1; n+=1024)
        g_s1[nb+n] = gth16(sX, s16, w, n);
}
__global__ void __launch_bounds__(1024) k_ls2(const float* __restrict__ ew){
    __shared__ float sX[NEe];
    int g = blockIdx.x>>1, ch = blockIdx.x&1, tid = threadIdx.x;
    long nb = (long)g*NEe;
    for (int n=tid;n<NEe;n+=1024) sX[n] = g_s1[nb+n];
    __syncthreads();
    const unsigned short* s16 = g_u16a + nb*16;
    const float* w = ew + nb*16;
    int n1 = ch*CHK0+CHK0; if (n1>NEe) n1=NEe;
    for (int n=ch*CHK0+tid; n<n1; n+=1024)
        g_s2[nb+n] = gth16(sX, s16, w, n);
}
__global__ void __launch_bounds__(1024) k_ls3(const float* __restrict__ x,
                                              const float* __restrict__ ew){
    __shared__ float sX[NEe];
    __shared__ float shst[14];
    int g = blockIdx.x>>1, ch = blockIdx.x&1, tid = threadIdx.x;
    long nb = (long)g*NEe;
    if (tid<14) shst[tid]=0.f;
    for (int n=tid;n<NEe;n+=1024) sX[n] = g_s2[nb+n];
    __syncthreads();
    const unsigned short* s16 = g_u16a + nb*16;
    const float* w = ew + nb*16;
    int n1 = ch*CHK0+CHK0; if (n1>NEe) n1=NEe;
    float st[14];
    #pragma unroll
    for (int j=0;j<14;j++) st[j]=0.f;
    for (int n=ch*CHK0+tid; n<n1; n+=1024){
        float a = gth16(sX, s16, w, n);
        g_s3[nb+n]=a;
        float v0=__ldg(x+nb+n), v1=g_s1[nb+n], v2=sX[n], v3=a;
        st[0]+=v0; st[1]+=v1; st[2]+=v2; st[3]+=v3;
        st[4]+=v0*v0; st[5]+=v0*v1; st[6]+=v0*v2; st[7]+=v0*v3;
        st[8]+=v1*v1; st[9]+=v1*v2; st[10]+=v1*v3;
        st[11]+=v2*v2; st[12]+=v2*v3; st[13]+=v3*v3;
    }
    #pragma unroll
    for (int j=0;j<14;j++){
        #pragma unroll
        for (int r=16;r;r>>=1) st[j] += __shfl_xor_sync(0xffffffffu, st[j], r);
    }
    if ((tid&31)==0){
        #pragma unroll
        for (int j=0;j<14;j++) atomicAdd(&shst[j], st[j]);
    }
    __syncthreads();
    if (tid<14) atomicAdd(&g_st0[tid*16 + (blockIdx.x&15)], (double)shst[tid]);
}

__global__ void k_fin0(const float* __restrict__ b0, const float* __restrict__ g0,
                       const float* __restrict__ be0){
    int c = threadIdx.x; if (c>=32) return;
    double st[14];
    for (int j=0;j<14;j++){ double s=0; for (int q=0;q<16;q++) s+=g_st0[j*16+q]; st[j]=s; }
    double invN = 1.0/(double)NN1, mu[4];
    for (int m=0;m<4;m++) mu[m]=st[m]*invN;
    double cov[4][4]; int idx=4;
    for (int m=0;m<4;m++) for (int mm=m;mm<4;mm++){
        double cc = st[idx]*invN - mu[m]*mu[mm];
        cov[m][mm]=cc; cov[mm][m]=cc; idx++;
    }
    double a[4];
    for (int m=0;m<4;m++) a[m]=(double)g_a0[m*32+c];
    double proj=0, var=0;
    for (int m=0;m<4;m++) proj += mu[m]*a[m];
    for (int m=0;m<4;m++) for (int mm=0;mm<4;mm++) var += a[m]*a[mm]*cov[m][mm];
    double sc = (double)g0[c]/sqrt(var+1e-5);
    g_scale0[c]=(float)sc;
    g_shift0[c]=(float)((double)be0[c] - proj*sc);
}

// ---- pool + BN + LeakyReLU -> X1[N][32] (warp per node, lane = channel) ----
__global__ void __launch_bounds__(256) k_pool(const float* __restrict__ x){
    int w=(blockIdx.x*blockDim.x+threadIdx.x)>>5;
    int lane=threadIdx.x&31;
    int b = w/NE2e, e2 = w-b*NE2e; int m0 = b*NEe + 2*e2;
    float a0=g_a0[lane], a1=g_a0[32+lane], a2=g_a0[64+lane], a3=g_a0[96+lane];
    float sc=g_scale0[lane], sf=g_shift0[lane];
    float s0a=__ldg(x+m0),   s1a=g_s1[m0],   s2a=g_s2[m0],   s3a=g_s3[m0];
    float s0b=__ldg(x+m0+1), s1b=g_s1[m0+1], s2b=g_s2[m0+1], s3b=g_s3[m0+1];
    float ra = fmaf(s0a,a0, fmaf(s1a,a1, fmaf(s2a,a2, s3a*a3)));
    float rb = fmaf(s0b,a0, fmaf(s1b,a1, fmaf(s2b,a2, s3b*a3)));
    g_X1[(size_t)w*32+lane] = fmaxf(leaky(fmaf(ra,sc,sf)), leaky(fmaf(rb,sc,sf)));
}

// ---- mixing GEMM: Y[:,half*64..+64] = X1 @ A[:,half*64..+64], tile 64x64, 4x4/thread ----
__global__ void __launch_bounds__(256) k_mixgemm(){
    __shared__ float Xs[32*68];
    __shared__ float As[32*64];
    int tid=threadIdx.x;
    int tileN = blockIdx.x>>1, half = blockIdx.x&1;
    int nbase = tileN*64;
    for (int idx=tid; idx<2048; idx+=256){
        int node = idx>>5, c = idx&31;
        Xs[c*68 + node] = g_X1[(size_t)(nbase+node)*32 + c];
    }
    for (int idx=tid; idx<2048; idx+=256){
        int k = idx>>6, col = idx&63;
        int gcol = half*64 + col;
        As[idx] = g_A[(gcol>>5)*1024 + k*32 + (gcol&31)];
    }
    __syncthreads();
    int tr = tid&15, tc = tid>>4;
    float acc[4][4];
    #pragma unroll
    for (int r=0;r<4;r++)
        #pragma unroll
        for (int c=0;c<4;c++) acc[r][c]=0.f;
    #pragma unroll 4
    for (int k=0;k<32;k++){
        float4 xr = *reinterpret_cast<float4*>(&Xs[k*68 + 4*tr]);
        float4 av = *reinterpret_cast<float4*>(&As[k*64 + 4*tc]);
        float xv[4]={xr.x,xr.y,xr.z,xr.w};
        float aw[4]={av.x,av.y,av.z,av.w};
        #pragma unroll
        for (int r=0;r<4;r++)
            #pragma unroll
            for (int c=0;c<4;c++) acc[r][c] = fmaf(xv[r], aw[c], acc[r][c]);
    }
    int gcol0 = half*64 + tc*4;
    float* Yp = g_Y + (size_t)(gcol0>>5)*YSZ;
    int cc = gcol0&31;
    #pragma unroll
    for (int r=0;r<4;r++){
        size_t base = (size_t)(nbase + 4*tr + r)*32 + cc;
        *reinterpret_cast<float4*>(&Yp[base]) =
            make_float4(acc[r][0],acc[r][1],acc[r][2],acc[r][3]);
    }
}

// ---- 32-ch matvec: 2 nodes per warp ----
__global__ void __launch_bounds__(256) k_mvA(const int* __restrict__ src,
                                             const float* __restrict__ ew){
    __shared__ int ss[8][32]; __shared__ float sw[8][32];
    int tid=threadIdx.x, lane=tid&31, wid=tid>>5;
    int n0 = blockIdx.x*16 + wid*2;
    ss[wid][lane]=src[n0*16+lane]; sw[wid][lane]=ew[n0*16+lane];
    __syncwarp();
    const float* v = g_Y + 3*YSZ;
    float acc0 = g_Y[2*YSZ + (size_t)n0*32+lane];
    float acc1 = g_Y[2*YSZ + (size_t)(n0+1)*32+lane];
    #pragma unroll
    for (int j=0;j<16;j++){
        acc0 = fmaf(sw[wid][j],    __ldg(v + (size_t)ss[wid][j]*32 + lane), acc0);
        acc1 = fmaf(sw[wid][16+j], __ldg(v + (size_t)ss[wid][16+j]*32 + lane), acc1);
    }
    g_R1[(size_t)n0*32+lane]=acc0;
    g_R1[(size_t)(n0+1)*32+lane]=acc1;
}
__global__ void __launch_bounds__(256) k_mvB(const int* __restrict__ src,
                                             const float* __restrict__ ew){
    __shared__ int ss[8][32]; __shared__ float sw[8][32];
    int tid=threadIdx.x, lane=tid&31, wid=tid>>5;
    int n0 = blockIdx.x*16 + wid*2;
    ss[wid][lane]=src[n0*16+lane]; sw[wid][lane]=ew[n0*16+lane];
    __syncwarp();
    float acc0 = g_Y[YSZ + (size_t)n0*32+lane];
    float acc1 = g_Y[YSZ + (size_t)(n0+1)*32+lane];
    #pragma unroll
    for (int j=0;j<16;j++){
        acc0 = fmaf(sw[wid][j],    __ldg(g_R1 + (size_t)ss[wid][j]*32 + lane), acc0);
        acc1 = fmaf(sw[wid][16+j], __ldg(g_R1 + (size_t)ss[wid][16+j]*32 + lane), acc1);
    }
    g_R2[(size_t)n0*32+lane]=acc0;
    g_R2[(size_t)(n0+1)*32+lane]=acc1;
}

__global__ void __launch_bounds__(256) k_mvC(const int* __restrict__ src,
        const float* __restrict__ ew, const float* __restrict__ b1){
    __shared__ int   ss[8][16];
    __shared__ float sw[8][16];
    __shared__ float sum_s[32], sq_s[32];
    int tid=threadIdx.x, lane=tid&31, wid=tid>>5;
    if (tid<32){ sum_s[tid]=0.f; sq_s[tid]=0.f; }
    __syncthreads();
    float bias = __ldg(b1+lane);
    int w0 = blockIdx.x*8 + wid, nw = gridDim.x*8;
    float ps=0.f, pq=0.f;
    for (int n=w0; n<NN2; n+=nw){
        if (lane<16) ss[wid][lane] = src[n*16+lane];
        else         sw[wid][lane-16] = ew[n*16+lane-16];
        __syncwarp();
        float acc = g_Y[(size_t)n*32+lane] + bias;
        #pragma unroll
        for (int j=0;j<16;j++)
            acc = fmaf(sw[wid][j], __ldg(g_R2 + (size_t)ss[wid][j]*32 + lane), acc);
        g_O1[(size_t)n*32+lane] = acc;
        ps += acc; pq += acc*acc;
        __syncwarp();
    }
    atomicAdd(&sum_s[lane], ps); atomicAdd(&sq_s[lane], pq);
    __syncthreads();
    if (tid<32){
        int slot = blockIdx.x&15;
        atomicAdd(&g_sum1[tid*16+slot], (double)sum_s[tid]);
        atomicAdd(&g_sq1[tid*16+slot],  (double)sq_s[tid]);
    }
}

__global__ void k_fin1(const float* __restrict__ g1, const float* __restrict__ be1){
    int c=threadIdx.x; if (c>=32) return;
    double s=0,q=0;
    for (int slot=0;slot<16;slot++){ s+=g_sum1[c*16+slot]; q+=g_sq1[c*16+slot]; }
    double invN = 1.0/(double)NN2;
    double mean=s*invN, var=q*invN-mean*mean;
    double sc=(double)g1[c]/sqrt(var+1e-5);
    g_scale1[c]=(float)sc; g_shift1[c]=(float)((double)be1[c]-mean*sc);
}

__global__ void k_mix2(){
    int w=(blockIdx.x*blockDim.x+threadIdx.x)>>5; if (w>=NN2) return;
    int lane=threadIdx.x&31;
    float o=g_O1[(size_t)w*32+lane];
    float x2=leaky(fmaf(g_scale1[lane], o, g_shift1[lane]));
    float p0=x2*g_aV[lane],     p1=x2*g_aV[32+lane];
    float p2=x2*g_aV[64+lane],  p3=x2*g_aV[96+lane];
    #pragma unroll
    for (int r=16;r;r>>=1){
        p0+=__shfl_xor_sync(0xffffffffu,p0,r); p1+=__shfl_xor_sync(0xffffffffu,p1,r);
        p2+=__shfl_xor_sync(0xffffffffu,p2,r); p3+=__shfl_xor_sync(0xffffffffu,p3,r);
    }
    if (lane==0){ g_w0[w]=p0; g_w1[w]=p1; g_w2[w]=p2; g_w3[w]=p3; }
}

__global__ void k_sc1(const int* __restrict__ src, const float* __restrict__ ew){
    int i = blockIdx.x*blockDim.x+threadIdx.x; if (i>=NN2) return;
    float a=g_w2[i]; smv_body(i, g_w3, src, ew, a); g_r1[i]=a;
}
__global__ void k_sc2(const int* __restrict__ src, const float* __restrict__ ew){
    int i = blockIdx.x*blockDim.x+threadIdx.x; if (i>=NN2) return;
    float a=g_w1[i]; smv_body(i, g_r1, src, ew, a); g_r2[i]=a;
}
__global__ void k_sc3(const int* __restrict__ src, const float* __restrict__ ew,
                      const float* __restrict__ b2){
    int stride = gridDim.x*blockDim.x;
    float bias=__ldg(b2);
    float ps=0.f,pq=0.f;
    for (int i = blockIdx.x*blockDim.x+threadIdx.x; i<NN2; i+=stride){
        float a=g_w0[i]+bias; smv_body(i, g_r2, src, ew, a);
        g_raw2[i]=a; ps+=a; pq+=a*a;
    }
    __shared__ float sh[2];
    if (threadIdx.x<2) sh[threadIdx.x]=0.f;
    __syncthreads();
    #pragma unroll
    for (int r=16;r;r>>=1){ ps+=__shfl_xor_sync(0xffffffffu,ps,r); pq+=__shfl_xor_sync(0xffffffffu,pq,r); }
    if ((threadIdx.x&31)==0){ atomicAdd(&sh[0],ps); atomicAdd(&sh[1],pq); }
    __syncthreads();
    if (threadIdx.x<2)
        atomicAdd(&g_st2[threadIdx.x*16 + (blockIdx.x&15)], (double)sh[threadIdx.x]);
}

__global__ void k_finS(const float* __restrict__ g2, const float* __restrict__ be2){
    if (threadIdx.x!=0) return;
    double s=0,q=0;
    for (int slot=0;slot<16;slot++){ s+=g_st2[slot]; q+=g_st2[16+slot]; }
    double invN=1.0/(double)NN2;
    double mean=s*invN, var=q*invN-mean*mean;
    double sc=(double)g2[0]/sqrt(var+1e-5);
    g_bn2s[0]=(float)sc; g_bn2s[1]=(float)((double)be2[0]-mean*sc);
}

__global__ void __launch_bounds__(256) k_mlp1(const float* __restrict__ W,
                                              const float* __restrict__ bb){
    extern __shared__ float sA[];
    int tid = threadIdx.x;
    int cb = blockIdx.x & 7, kc = blockIdx.x >> 3;
    int k0 = kc*MCHK;
    int klen = NE2e - k0; if (klen > MCHK) klen = MCHK;
    float sc = g_bn2s[0], sf = g_bn2s[1];
    for (int idx=tid; idx<64*klen; idx+=256){
        int r = idx / klen, k = idx - r*klen;
        sA[r*MCHK + k] = leaky(fmaf(g_raw2[(long)r*NE2e + k0 + k], sc, sf));
    }
    __syncthreads();
    int col = cb*32 + (tid&31);
    int r0 = (tid>>5)*8;
    float acc[8];
    #pragma unroll
    for (int r=0;r<8;r++) acc[r]=0.f;
    for (int k=0;k<klen;k++){
        float wv = __ldg(W + (long)(k0+k)*256 + col);
        #pragma unroll
        for (int r=0;r<8;r++) acc[r] = fmaf(sA[(r0+r)*MCHK + k], wv, acc[r]);
    }
    float bias = (kc==0) ? __ldg(bb+col) : 0.f;
    #pragma unroll
    for (int r=0;r<8;r++) atomicAdd(&g_h1raw[(r0+r)*256 + col], acc[r] + bias);
}

__global__ void k_bn1(const float* __restrict__ g, const float* __restrict__ be){
    int c=threadIdx.x;
    float s=0.f,q=0.f;
    #pragma unroll 8
    for (int b=0;b<64;b++){ float v=g_h1raw[b*256+c]; s+=v; q+=v*v; }
    float mean=s*(1.f/64.f), var=q*(1.f/64.f)-mean*mean;
    float sc=__ldg(g+c)*rsqrtf(var+1e-5f), sf=__ldg(be+c)-mean*sc;
    for (int b=0;b<64;b++){
        float v=fmaf(g_h1raw[b*256+c],sc,sf);
        g_h1[b*256+c]= v>0.f? v:0.f;
    }
}

__global__ void k_mlp2(const float* __restrict__ W, const float* __restrict__ bb){
    __shared__ float shx[256];
    int b = blockIdx.x, t = threadIdx.x;
    for (int i=t;i<256;i+=128) shx[i]=g_h1[b*256+i];
    __syncthreads();
    float acc=__ldg(bb+t);
    #pragma unroll 8
    for (int i=0;i<256;i++) acc = fmaf(shx[i], __ldg(W+i*128+t), acc);
    g_h2raw[b*128+t]=acc;
}

__global__ void k_bn2out(const float* __restrict__ g, const float* __restrict__ be,
                         const float* __restrict__ W3, const float* __restrict__ b3,
                         float* __restrict__ out){
    __shared__ float sh2[64*128];
    int c=threadIdx.x;
    float s=0.f,q=0.f;
    #pragma unroll 8
    for (int b=0;b<64;b++){ float v=g_h2raw[b*128+c]; s+=v; q+=v*v; }
    float mean=s*(1.f/64.f), var=q*(1.f/64.f)-mean*mean;
    float sc=__ldg(g+c)*rsqrtf(var+1e-5f), sf=__ldg(be+c)-mean*sc;
    for (int b=0;b<64;b++){
        float v=fmaf(g_h2raw[b*128+c],sc,sf);
        sh2[b*128+c]= v>0.f? v:0.f;
    }
    __syncthreads();
    if (c<64){
        float acc=__ldg(b3);
        #pragma unroll 8
        for (int j=0;j<128;j++) acc=fmaf(sh2[c*128+j], __ldg(W3+j), acc);
        out[c]=acc;
    }
}

extern "C" void kernel_launch(void* const* d_in, const int* in_sizes, int n_in,
                              void* d_out, int out_size){
    const float* x_s  = (const float*)d_in[0];
    const int*   ei1  = (const int*)d_in[1];
    const float* ew1  = (const float*)d_in[2];
    const int*   ei2  = (const int*)d_in[3];
    const float* ew2  = (const float*)d_in[4];
    const float* W0   = (const float*)d_in[5];
    const float* b0   = (const float*)d_in[6];
    const float* g0   = (const float*)d_in[7];
    const float* be0  = (const float*)d_in[8];
    const float* W1   = (const float*)d_in[9];
    const float* b1   = (const float*)d_in[10];
    const float* g1   = (const float*)d_in[11];
    const float* be1  = (const float*)d_in[12];
    const float* W2   = (const float*)d_in[13];
    const float* b2   = (const float*)d_in[14];
    const float* g2   = (const float*)d_in[15];
    const float* be2  = (const float*)d_in[16];
    const float* l1W  = (const float*)d_in[17];
    const float* l1b  = (const float*)d_in[18];
    const float* bn1g = (const float*)d_in[19];
    const float* bn1b = (const float*)d_in[20];
    const float* l2W  = (const float*)d_in[21];
    const float* l2b  = (const float*)d_in[22];
    const float* bn2g = (const float*)d_in[23];
    const float* bn2b = (const float*)d_in[24];
    const float* l3W  = (const float*)d_in[25];
    const float* l3b  = (const float*)d_in[26];
    float* out = (float*)d_out;

    const int smM1 = 64*MCHK*(int)sizeof(float);
    static int init = 0;
    if (!init){
        cudaFuncSetAttribute(k_mlp1, cudaFuncAttributeMaxDynamicSharedMemorySize, smM1);
        init = 1;
    }

    k_prep<<<256,256>>>(W0, W1, W2, ei1);
    k_ls1<<<128,1024>>>(x_s, ew1);
    k_ls2<<<128,1024>>>(ew1);
    k_ls3<<<128,1024>>>(x_s, ew1);
    k_fin0<<<1,32>>>(b0, g0, be0);
    k_pool<<<NN2/8,256>>>(x_s);
    k_mixgemm<<<(NN2/64)*2,256>>>();
    k_mvA<<<NN2/16,256>>>(ei2, ew2);
    k_mvB<<<NN2/16,256>>>(ei2, ew2);
    k_mvC<<<GSB,256>>>(ei2, ew2, b1);
    k_fin1<<<1,32>>>(g1, be1);
    k_mix2<<<(NN2*32+255)/256,256>>>();
    int nb2 = (NN2+255)/256;
    k_sc1<<<nb2,256>>>(ei2, ew2);
    k_sc2<<<nb2,256>>>(ei2, ew2);
    k_sc3<<<GSB,256>>>(ei2, ew2, b2);
    k_finS<<<1,32>>>(g2, be2);
    k_mlp1<<<64,256,smM1>>>(l1W, l1b);
    k_bn1<<<1,256>>>(bn1g, bn1b);
    k_mlp2<<<64,128>>>(l2W, l2b);
    k_bn2out<<<1,128>>>(bn2g, bn2b, l3W, l3b, out);
}

// round 16
// speedup vs baseline: 1.1000x; 1.0484x over previous
#include <cuda_runtime.h>

#define NB 64
#define NEe 8978
#define NE2e 4489
#define NN1 (NB*NEe)
#define NN2 (NB*NE2e)
#define NEDGE1 (NN1*16)
#define SLOPEc 0.33f
#define GSB 1184
#define MCHK 562
#define CHK0 4489
#define YSZ ((size_t)NN2*32)

__device__ float g_s1[NN1], g_s2[NN1], g_s3[NN1];
__device__ float g_Y[4*NN2*32];
__device__ float g_R1[NN2*32], g_R2[NN2*32], g_O1[NN2*32];
__device__ float g_w0[NN2], g_w1[NN2], g_w2[NN2], g_w3[NN2];
__device__ float g_r1[NN2], g_r2[NN2], g_raw2[NN2];
__device__ float g_A[4096], g_a0[128], g_aV[128];
__device__ double g_st0[14*16], g_sum1[32*16], g_sq1[32*16], g_st2[2*16];
__device__ float g_scale0[32], g_shift0[32], g_scale1[32], g_shift1[32], g_bn2s[2];
__device__ float g_h1raw[64*256], g_h1[64*256], g_h2raw[64*128];
__device__ unsigned short g_u16a[NEDGE1];

__constant__ float c_C[16] = {1.f,0.f,0.f,0.f, 1.f,-1.f,0.f,0.f,
                              1.f,-2.f,0.5f,0.f, 1.f,-3.f,1.5f,-0.16666666666666666f};

__device__ __forceinline__ float leaky(float v){ return v>0.f? v : SLOPEc*v; }

__global__ void k_prep(const float* __restrict__ W0, const float* __restrict__ W1,
                       const float* __restrict__ W2, const int* __restrict__ src1){
    int t = blockIdx.x*blockDim.x + threadIdx.x, stride = gridDim.x*blockDim.x;
    for (int i=t;i<NEDGE1;i+=stride)
        g_u16a[i]=(unsigned short)(src1[i]-(i/(NEe*16))*NEe);
    for (int idx=t; idx<4096; idx+=stride){
        int m = idx>>10, ic = idx&1023;
        float s=0.f;
        #pragma unroll
        for (int k=0;k<4;k++) s = fmaf(c_C[k*4+m], W1[k*1024+ic], s);
        g_A[idx]=s;
    }
    for (int idx=t; idx<128; idx+=stride){
        int m = idx>>5, c = idx&31;
        float s0=0.f, sv=0.f;
        #pragma unroll
        for (int k=0;k<4;k++){
            float cc = c_C[k*4+m];
            s0 = fmaf(cc, W0[k*32+c], s0);
            sv = fmaf(cc, W2[k*32+c], sv);
        }
        g_a0[idx]=s0; g_aV[idx]=sv;
    }
    for (int idx=t; idx<14*16; idx+=stride) g_st0[idx]=0.0;
    for (int idx=t; idx<32*16; idx+=stride){ g_sum1[idx]=0.0; g_sq1[idx]=0.0; }
    for (int idx=t; idx<2*16;  idx+=stride) g_st2[idx]=0.0;
    for (int idx=t; idx<64*256; idx+=stride) g_h1raw[idx]=0.f;
}

__device__ __forceinline__ void smv_body(int i, const float* __restrict__ v,
                                         const int* __restrict__ src,
                                         const float* __restrict__ ew, float& acc){
    const int4*   sp = reinterpret_cast<const int4*>(src) + i*4;
    const float4* wp = reinterpret_cast<const float4*>(ew) + i*4;
    #pragma unroll
    for (int q=0;q<4;q++){
        int4 s = __ldg(sp+q); float4 w = __ldg(wp+q);
        acc = fmaf(w.x, __ldg(v+s.x), acc);
        acc = fmaf(w.y, __ldg(v+s.y), acc);
        acc = fmaf(w.z, __ldg(v+s.z), acc);
        acc = fmaf(w.w, __ldg(v+s.w), acc);
    }
}

__device__ __forceinline__ float gth16(const float* __restrict__ sbuf,
        const unsigned short* __restrict__ s16, const float* __restrict__ w, int n){
    float acc=0.f;
    const ushort4* sp = reinterpret_cast<const ushort4*>(s16) + n*4;
    const float4*  wp = reinterpret_cast<const float4*>(w) + n*4;
    #pragma unroll
    for (int q=0;q<4;q++){
        ushort4 s = sp[q]; float4 ww = __ldg(wp+q);
        acc = fmaf(ww.x, sbuf[s.x], acc);
        acc = fmaf(ww.y, sbuf[s.y], acc);
        acc = fmaf(ww.z, sbuf[s.z], acc);
        acc = fmaf(ww.w, sbuf[s.w], acc);
    }
    return acc;
}

// ---- layer 0: 2 chunks per graph, 1024 threads ----
__global__ void __launch_bounds__(1024) k_ls1(const float* __restrict__ x,
                                              const float* __restrict__ ew){
    __shared__ float sX[NEe];
    int g = blockIdx.x>>1, ch = blockIdx.x&1, tid = threadIdx.x;
    long nb = (long)g*NEe;
    for (int n=tid;n<NEe;n+=1024) sX[n] = __ldg(x+nb+n);
    __syncthreads();
    const unsigned short* s16 = g_u16a + nb*16;
    const float* w = ew + nb*16;
    int n1 = ch*CHK0+CHK0; if (n1>NEe) n1=NEe;
    for (int n=ch*CHK0+tid; n<n1; n+=1024)
        g_s1[nb+n] = gth16(sX, s16, w, n);
}
__global__ void __launch_bounds__(1024) k_ls2(const float* __restrict__ ew){
    __shared__ float sX[NEe];
    int g = blockIdx.x>>1, ch = blockIdx.x&1, tid = threadIdx.x;
    long nb = (long)g*NEe;
    for (int n=tid;n<NEe;n+=1024) sX[n] = g_s1[nb+n];
    __syncthreads();
    const unsigned short* s16 = g_u16a + nb*16;
    const float* w = ew + nb*16;
    int n1 = ch*CHK0+CHK0; if (n1>NEe) n1=NEe;
    for (int n=ch*CHK0+tid; n<n1; n+=1024)
        g_s2[nb+n] = gth16(sX, s16, w, n);
}
__global__ void __launch_bounds__(1024) k_ls3(const float* __restrict__ x,
                                              const float* __restrict__ ew){
    __shared__ float sX[NEe];
    __shared__ float shst[14];
    int g = blockIdx.x>>1, ch = blockIdx.x&1, tid = threadIdx.x;
    long nb = (long)g*NEe;
    if (tid<14) shst[tid]=0.f;
    for (int n=tid;n<NEe;n+=1024) sX[n] = g_s2[nb+n];
    __syncthreads();
    const unsigned short* s16 = g_u16a + nb*16;
    const float* w = ew + nb*16;
    int n1 = ch*CHK0+CHK0; if (n1>NEe) n1=NEe;
    float st[14];
    #pragma unroll
    for (int j=0;j<14;j++) st[j]=0.f;
    for (int n=ch*CHK0+tid; n<n1; n+=1024){
        float a = gth16(sX, s16, w, n);
        g_s3[nb+n]=a;
        float v0=__ldg(x+nb+n), v1=g_s1[nb+n], v2=sX[n], v3=a;
        st[0]+=v0; st[1]+=v1; st[2]+=v2; st[3]+=v3;
        st[4]+=v0*v0; st[5]+=v0*v1; st[6]+=v0*v2; st[7]+=v0*v3;
        st[8]+=v1*v1; st[9]+=v1*v2; st[10]+=v1*v3;
        st[11]+=v2*v2; st[12]+=v2*v3; st[13]+=v3*v3;
    }
    #pragma unroll
    for (int j=0;j<14;j++){
        #pragma unroll
        for (int r=16;r;r>>=1) st[j] += __shfl_xor_sync(0xffffffffu, st[j], r);
    }
    if ((tid&31)==0){
        #pragma unroll
        for (int j=0;j<14;j++) atomicAdd(&shst[j], st[j]);
    }
    __syncthreads();
    if (tid<14) atomicAdd(&g_st0[tid*16 + (blockIdx.x&15)], (double)shst[tid]);
}

__global__ void k_fin0(const float* __restrict__ b0, const float* __restrict__ g0,
                       const float* __restrict__ be0){
    int c = threadIdx.x; if (c>=32) return;
    double st[14];
    for (int j=0;j<14;j++){ double s=0; for (int q=0;q<16;q++) s+=g_st0[j*16+q]; st[j]=s; }
    double invN = 1.0/(double)NN1, mu[4];
    for (int m=0;m<4;m++) mu[m]=st[m]*invN;
    double cov[4][4]; int idx=4;
    for (int m=0;m<4;m++) for (int mm=m;mm<4;mm++){
        double cc = st[idx]*invN - mu[m]*mu[mm];
        cov[m][mm]=cc; cov[mm][m]=cc; idx++;
    }
    double a[4];
    for (int m=0;m<4;m++) a[m]=(double)g_a0[m*32+c];
    double proj=0, var=0;
    for (int m=0;m<4;m++) proj += mu[m]*a[m];
    for (int m=0;m<4;m++) for (int mm=0;mm<4;mm++) var += a[m]*a[mm]*cov[m][mm];
    double sc = (double)g0[c]/sqrt(var+1e-5);
    g_scale0[c]=(float)sc;
    g_shift0[c]=(float)((double)be0[c] - proj*sc);
}

// ---- fused pool + BN + mix as tiled GEMM (proven 107us variant) ----
__global__ void __launch_bounds__(256) k_poolmix(const float* __restrict__ x){
    __shared__ float Xs[32*68];
    __shared__ float As[32*128];
    int tid=threadIdx.x, lane=tid&31, wid=tid>>5;
    for (int idx=tid; idx<4096; idx+=256){
        int k=idx>>7, col=idx&127, m=col>>5, c=col&31;
        As[idx] = g_A[m*1024 + k*32 + c];
    }
    float a0=g_a0[lane], a1=g_a0[32+lane], a2=g_a0[64+lane], a3=g_a0[96+lane];
    float sc=g_scale0[lane], sf=g_shift0[lane];
    int nbase = blockIdx.x*64;
    #pragma unroll
    for (int j=0;j<8;j++){
        int nl = wid*8+j, n = nbase+nl;
        int b = n/NE2e, e2 = n-b*NE2e; int m0 = b*NEe + 2*e2;
        float s0a=__ldg(x+m0),   s1a=g_s1[m0],   s2a=g_s2[m0],   s3a=g_s3[m0];
        float s0b=__ldg(x+m0+1), s1b=g_s1[m0+1], s2b=g_s2[m0+1], s3b=g_s3[m0+1];
        float ra = fmaf(s0a,a0, fmaf(s1a,a1, fmaf(s2a,a2, s3a*a3)));
        float rb = fmaf(s0b,a0, fmaf(s1b,a1, fmaf(s2b,a2, s3b*a3)));
        Xs[lane*68 + nl] = fmaxf(leaky(fmaf(ra,sc,sf)), leaky(fmaf(rb,sc,sf)));
    }
    __syncthreads();
    int tr = tid&15, tcg = tid>>4;
    float acc[4][8];
    #pragma unroll
    for (int r=0;r<4;r++)
        #pragma unroll
        for (int c=0;c<8;c++) acc[r][c]=0.f;
    #pragma unroll 4
    for (int k=0;k<32;k++){
        float4 xr = *reinterpret_cast<float4*>(&Xs[k*68 + 4*tr]);
        float4 av0 = *reinterpret_cast<float4*>(&As[k*128 + 8*tcg]);
        float4 av1 = *reinterpret_cast<float4*>(&As[k*128 + 8*tcg + 4]);
        float xv[4] = {xr.x, xr.y, xr.z, xr.w};
        float av[8] = {av0.x,av0.y,av0.z,av0.w, av1.x,av1.y,av1.z,av1.w};
        #pragma unroll
        for (int r=0;r<4;r++)
            #pragma unroll
            for (int c=0;c<8;c++) acc[r][c] = fmaf(xv[r], av[c], acc[r][c]);
    }
    int m = tcg>>2, cc = (tcg&3)*8;
    float* Yp = g_Y + (size_t)m*YSZ;
    #pragma unroll
    for (int r=0;r<4;r++){
        size_t base = (size_t)(nbase + 4*tr + r)*32 + cc;
        *reinterpret_cast<float4*>(&Yp[base])   = make_float4(acc[r][0],acc[r][1],acc[r][2],acc[r][3]);
        *reinterpret_cast<float4*>(&Yp[base+4]) = make_float4(acc[r][4],acc[r][5],acc[r][6],acc[r][7]);
    }
}

// ---- 32-ch matvec: 2 nodes per warp ----
__global__ void __launch_bounds__(256) k_mvA(const int* __restrict__ src,
                                             const float* __restrict__ ew){
    __shared__ int ss[8][32]; __shared__ float sw[8][32];
    int tid=threadIdx.x, lane=tid&31, wid=tid>>5;
    int n0 = blockIdx.x*16 + wid*2;
    ss[wid][lane]=src[n0*16+lane]; sw[wid][lane]=ew[n0*16+lane];
    __syncwarp();
    const float* v = g_Y + 3*YSZ;
    float acc0 = g_Y[2*YSZ + (size_t)n0*32+lane];
    float acc1 = g_Y[2*YSZ + (size_t)(n0+1)*32+lane];
    #pragma unroll
    for (int j=0;j<16;j++){
        acc0 = fmaf(sw[wid][j],    __ldg(v + (size_t)ss[wid][j]*32 + lane), acc0);
        acc1 = fmaf(sw[wid][16+j], __ldg(v + (size_t)ss[wid][16+j]*32 + lane), acc1);
    }
    g_R1[(size_t)n0*32+lane]=acc0;
    g_R1[(size_t)(n0+1)*32+lane]=acc1;
}
__global__ void __launch_bounds__(256) k_mvB(const int* __restrict__ src,
                                             const float* __restrict__ ew){
    __shared__ int ss[8][32]; __shared__ float sw[8][32];
    int tid=threadIdx.x, lane=tid&31, wid=tid>>5;
    int n0 = blockIdx.x*16 + wid*2;
    ss[wid][lane]=src[n0*16+lane]; sw[wid][lane]=ew[n0*16+lane];
    __syncwarp();
    float acc0 = g_Y[YSZ + (size_t)n0*32+lane];
    float acc1 = g_Y[YSZ + (size_t)(n0+1)*32+lane];
    #pragma unroll
    for (int j=0;j<16;j++){
        acc0 = fmaf(sw[wid][j],    __ldg(g_R1 + (size_t)ss[wid][j]*32 + lane), acc0);
        acc1 = fmaf(sw[wid][16+j], __ldg(g_R1 + (size_t)ss[wid][16+j]*32 + lane), acc1);
    }
    g_R2[(size_t)n0*32+lane]=acc0;
    g_R2[(size_t)(n0+1)*32+lane]=acc1;
}

__global__ void __launch_bounds__(256) k_mvC(const int* __restrict__ src,
        const float* __restrict__ ew, const float* __restrict__ b1){
    __shared__ int   ss[8][16];
    __shared__ float sw[8][16];
    __shared__ float sum_s[32], sq_s[32];
    int tid=threadIdx.x, lane=tid&31, wid=tid>>5;
    if (tid<32){ sum_s[tid]=0.f; sq_s[tid]=0.f; }
    __syncthreads();
    float bias = __ldg(b1+lane);
    int w0 = blockIdx.x*8 + wid, nw = gridDim.x*8;
    float ps=0.f, pq=0.f;
    for (int n=w0; n<NN2; n+=nw){
        if (lane<16) ss[wid][lane] = src[n*16+lane];
        else         sw[wid][lane-16] = ew[n*16+lane-16];
        __syncwarp();
        float acc = g_Y[(size_t)n*32+lane] + bias;
        #pragma unroll
        for (int j=0;j<16;j++)
            acc = fmaf(sw[wid][j], __ldg(g_R2 + (size_t)ss[wid][j]*32 + lane), acc);
        g_O1[(size_t)n*32+lane] = acc;
        ps += acc; pq += acc*acc;
        __syncwarp();
    }
    atomicAdd(&sum_s[lane], ps); atomicAdd(&sq_s[lane], pq);
    __syncthreads();
    if (tid<32){
        int slot = blockIdx.x&15;
        atomicAdd(&g_sum1[tid*16+slot], (double)sum_s[tid]);
        atomicAdd(&g_sq1[tid*16+slot],  (double)sq_s[tid]);
    }
}

__global__ void k_fin1(const float* __restrict__ g1, const float* __restrict__ be1){
    int c=threadIdx.x; if (c>=32) return;
    double s=0,q=0;
    for (int slot=0;slot<16;slot++){ s+=g_sum1[c*16+slot]; q+=g_sq1[c*16+slot]; }
    double invN = 1.0/(double)NN2;
    double mean=s*invN, var=q*invN-mean*mean;
    double sc=(double)g1[c]/sqrt(var+1e-5);
    g_scale1[c]=(float)sc; g_shift1[c]=(float)((double)be1[c]-mean*sc);
}

__global__ void k_mix2(){
    int w=(blockIdx.x*blockDim.x+threadIdx.x)>>5; if (w>=NN2) return;
    int lane=threadIdx.x&31;
    float o=g_O1[(size_t)w*32+lane];
    float x2=leaky(fmaf(g_scale1[lane], o, g_shift1[lane]));
    float p0=x2*g_aV[lane],     p1=x2*g_aV[32+lane];
    float p2=x2*g_aV[64+lane],  p3=x2*g_aV[96+lane];
    #pragma unroll
    for (int r=16;r;r>>=1){
        p0+=__shfl_xor_sync(0xffffffffu,p0,r); p1+=__shfl_xor_sync(0xffffffffu,p1,r);
        p2+=__shfl_xor_sync(0xffffffffu,p2,r); p3+=__shfl_xor_sync(0xffffffffu,p3,r);
    }
    if (lane==0){ g_w0[w]=p0; g_w1[w]=p1; g_w2[w]=p2; g_w3[w]=p3; }
}

__global__ void k_sc1(const int* __restrict__ src, const float* __restrict__ ew){
    int i = blockIdx.x*blockDim.x+threadIdx.x; if (i>=NN2) return;
    float a=g_w2[i]; smv_body(i, g_w3, src, ew, a); g_r1[i]=a;
}
__global__ void k_sc2(const int* __restrict__ src, const float* __restrict__ ew){
    int i = blockIdx.x*blockDim.x+threadIdx.x; if (i>=NN2) return;
    float a=g_w1[i]; smv_body(i, g_r1, src, ew, a); g_r2[i]=a;
}
__global__ void k_sc3(const int* __restrict__ src, const float* __restrict__ ew,
                      const float* __restrict__ b2){
    int stride = gridDim.x*blockDim.x;
    float bias=__ldg(b2);
    float ps=0.f,pq=0.f;
    for (int i = blockIdx.x*blockDim.x+threadIdx.x; i<NN2; i+=stride){
        float a=g_w0[i]+bias; smv_body(i, g_r2, src, ew, a);
        g_raw2[i]=a; ps+=a; pq+=a*a;
    }
    __shared__ float sh[2];
    if (threadIdx.x<2) sh[threadIdx.x]=0.f;
    __syncthreads();
    #pragma unroll
    for (int r=16;r;r>>=1){ ps+=__shfl_xor_sync(0xffffffffu,ps,r); pq+=__shfl_xor_sync(0xffffffffu,pq,r); }
    if ((threadIdx.x&31)==0){ atomicAdd(&sh[0],ps); atomicAdd(&sh[1],pq); }
    __syncthreads();
    if (threadIdx.x<2)
        atomicAdd(&g_st2[threadIdx.x*16 + (blockIdx.x&15)], (double)sh[threadIdx.x]);
}

__global__ void k_finS(const float* __restrict__ g2, const float* __restrict__ be2){
    if (threadIdx.x!=0) return;
    double s=0,q=0;
    for (int slot=0;slot<16;slot++){ s+=g_st2[slot]; q+=g_st2[16+slot]; }
    double invN=1.0/(double)NN2;
    double mean=s*invN, var=q*invN-mean*mean;
    double sc=(double)g2[0]/sqrt(var+1e-5);
    g_bn2s[0]=(float)sc; g_bn2s[1]=(float)((double)be2[0]-mean*sc);
}

__global__ void __launch_bounds__(256) k_mlp1(const float* __restrict__ W,
                                              const float* __restrict__ bb){
    extern __shared__ float sA[];
    int tid = threadIdx.x;
    int cb = blockIdx.x & 7, kc = blockIdx.x >> 3;
    int k0 = kc*MCHK;
    int klen = NE2e - k0; if (klen > MCHK) klen = MCHK;
    float sc = g_bn2s[0], sf = g_bn2s[1];
    for (int idx=tid; idx<64*klen; idx+=256){
        int r = idx / klen, k = idx - r*klen;
        sA[r*MCHK + k] = leaky(fmaf(g_raw2[(long)r*NE2e + k0 + k], sc, sf));
    }
    __syncthreads();
    int col = cb*32 + (tid&31);
    int r0 = (tid>>5)*8;
    float acc[8];
    #pragma unroll
    for (int r=0;r<8;r++) acc[r]=0.f;
    for (int k=0;k<klen;k++){
        float wv = __ldg(W + (long)(k0+k)*256 + col);
        #pragma unroll
        for (int r=0;r<8;r++) acc[r] = fmaf(sA[(r0+r)*MCHK + k], wv, acc[r]);
    }
    float bias = (kc==0) ? __ldg(bb+col) : 0.f;
    #pragma unroll
    for (int r=0;r<8;r++) atomicAdd(&g_h1raw[(r0+r)*256 + col], acc[r] + bias);
}

__global__ void k_bn1(const float* __restrict__ g, const float* __restrict__ be){
    int c=threadIdx.x;
    float s=0.f,q=0.f;
    #pragma unroll 8
    for (int b=0;b<64;b++){ float v=g_h1raw[b*256+c]; s+=v; q+=v*v; }
    float mean=s*(1.f/64.f), var=q*(1.f/64.f)-mean*mean;
    float sc=__ldg(g+c)*rsqrtf(var+1e-5f), sf=__ldg(be+c)-mean*sc;
    for (int b=0;b<64;b++){
        float v=fmaf(g_h1raw[b*256+c],sc,sf);
        g_h1[b*256+c]= v>0.f? v:0.f;
    }
}

__global__ void k_mlp2(const float* __restrict__ W, const float* __restrict__ bb){
    __shared__ float shx[256];
    int b = blockIdx.x, t = threadIdx.x;
    for (int i=t;i<256;i+=128) shx[i]=g_h1[b*256+i];
    __syncthreads();
    float acc=__ldg(bb+t);
    #pragma unroll 8
    for (int i=0;i<256;i++) acc = fmaf(shx[i], __ldg(W+i*128+t), acc);
    g_h2raw[b*128+t]=acc;
}

__global__ void k_bn2out(const float* __restrict__ g, const float* __restrict__ be,
                         const float* __restrict__ W3, const float* __restrict__ b3,
                         float* __restrict__ out){
    __shared__ float sh2[64*128];
    int c=threadIdx.x;
    float s=0.f,q=0.f;
    #pragma unroll 8
    for (int b=0;b<64;b++){ float v=g_h2raw[b*128+c]; s+=v; q+=v*v; }
    float mean=s*(1.f/64.f), var=q*(1.f/64.f)-mean*mean;
    float sc=__ldg(g+c)*rsqrtf(var+1e-5f), sf=__ldg(be+c)-mean*sc;
    for (int b=0;b<64;b++){
        float v=fmaf(g_h2raw[b*128+c],sc,sf);
        sh2[b*128+c]= v>0.f? v:0.f;
    }
    __syncthreads();
    if (c<64){
        float acc=__ldg(b3);
        #pragma unroll 8
        for (int j=0;j<128;j++) acc=fmaf(sh2[c*128+j], __ldg(W3+j), acc);
        out[c]=acc;
    }
}

extern "C" void kernel_launch(void* const* d_in, const int* in_sizes, int n_in,
                              void* d_out, int out_size){
    const float* x_s  = (const float*)d_in[0];
    const int*   ei1  = (const int*)d_in[1];
    const float* ew1  = (const float*)d_in[2];
    const int*   ei2  = (const int*)d_in[3];
    const float* ew2  = (const float*)d_in[4];
    const float* W0   = (const float*)d_in[5];
    const float* b0   = (const float*)d_in[6];
    const float* g0   = (const float*)d_in[7];
    const float* be0  = (const float*)d_in[8];
    const float* W1   = (const float*)d_in[9];
    const float* b1   = (const float*)d_in[10];
    const float* g1   = (const float*)d_in[11];
    const float* be1  = (const float*)d_in[12];
    const float* W2   = (const float*)d_in[13];
    const float* b2   = (const float*)d_in[14];
    const float* g2   = (const float*)d_in[15];
    const float* be2  = (const float*)d_in[16];
    const float* l1W  = (const float*)d_in[17];
    const float* l1b  = (const float*)d_in[18];
    const float* bn1g = (const float*)d_in[19];
    const float* bn1b = (const float*)d_in[20];
    const float* l2W  = (const float*)d_in[21];
    const float* l2b  = (const float*)d_in[22];
    const float* bn2g = (const float*)d_in[23];
    const float* bn2b = (const float*)d_in[24];
    const float* l3W  = (const float*)d_in[25];
    const float* l3b  = (const float*)d_in[26];
    float* out = (float*)d_out;

    const int smM1 = 64*MCHK*(int)sizeof(float);
    static int init = 0;
    if (!init){
        cudaFuncSetAttribute(k_mlp1, cudaFuncAttributeMaxDynamicSharedMemorySize, smM1);
        init = 1;
    }

    k_prep<<<256,256>>>(W0, W1, W2, ei1);
    k_ls1<<<128,1024>>>(x_s, ew1);
    k_ls2<<<128,1024>>>(ew1);
    k_ls3<<<128,1024>>>(x_s, ew1);
    k_fin0<<<1,32>>>(b0, g0, be0);
    k_poolmix<<<NN2/64,256>>>(x_s);
    k_mvA<<<NN2/16,256>>>(ei2, ew2);
    k_mvB<<<NN2/16,256>>>(ei2, ew2);
    k_mvC<<<GSB,256>>>(ei2, ew2, b1);
    k_fin1<<<1,32>>>(g1, be1);
    k_mix2<<<(NN2*32+255)/256,256>>>();
    int nb2 = (NN2+255)/256;
    k_sc1<<<nb2,256>>>(ei2, ew2);
    k_sc2<<<nb2,256>>>(ei2, ew2);
    k_sc3<<<GSB,256>>>(ei2, ew2, b2);
    k_finS<<<1,32>>>(g2, be2);
    k_mlp1<<<64,256,smM1>>>(l1W, l1b);
    k_bn1<<<1,256>>>(bn1g, bn1b);
    k_mlp2<<<64,128>>>(l2W, l2b);
    k_bn2out<<<1,128>>>(bn2g, bn2b, l3W, l3b, out);
}

// round 17
// speedup vs baseline: 1.1064x; 1.0057x over previous
#include <cuda_runtime.h>

#define NB 64
#define NEe 8978
#define NE2e 4489
#define NN1 (NB*NEe)
#define NN2 (NB*NE2e)
#define NEDGE1 (NN1*16)
#define SLOPEc 0.33f
#define GSB 1184
#define MCHK 562
#define CHK0 4489
#define YSZ ((size_t)NN2*32)

__device__ float g_s1[NN1], g_s2[NN1], g_s3[NN1];
__device__ float g_Y[4*NN2*32];
__device__ float g_R1[NN2*32], g_R2[NN2*32], g_O1[NN2*32];
__device__ float g_w0[NN2], g_w1[NN2], g_w2[NN2], g_w3[NN2];
__device__ float g_r1[NN2], g_r2[NN2], g_raw2[NN2];
__device__ float g_A[4096], g_a0[128], g_aV[128];
__device__ double g_st0[14*16], g_sum1[32*16], g_sq1[32*16], g_st2[2*16];
__device__ float g_scale0[32], g_shift0[32], g_scale1[32], g_shift1[32], g_bn2s[2];
__device__ float g_h1raw[64*256], g_h1[64*256], g_h2raw[64*128];
__device__ unsigned short g_u16a[NEDGE1];

__constant__ float c_C[16] = {1.f,0.f,0.f,0.f, 1.f,-1.f,0.f,0.f,
                              1.f,-2.f,0.5f,0.f, 1.f,-3.f,1.5f,-0.16666666666666666f};

__device__ __forceinline__ float leaky(float v){ return v>0.f? v : SLOPEc*v; }

__global__ void k_prep(const float* __restrict__ W0, const float* __restrict__ W1,
                       const float* __restrict__ W2, const int* __restrict__ src1){
    int t = blockIdx.x*blockDim.x + threadIdx.x, stride = gridDim.x*blockDim.x;
    for (int i=t;i<NEDGE1;i+=stride)
        g_u16a[i]=(unsigned short)(src1[i]-(i/(NEe*16))*NEe);
    for (int idx=t; idx<4096; idx+=stride){
        int m = idx>>10, ic = idx&1023;
        float s=0.f;
        #pragma unroll
        for (int k=0;k<4;k++) s = fmaf(c_C[k*4+m], W1[k*1024+ic], s);
        g_A[idx]=s;
    }
    for (int idx=t; idx<128; idx+=stride){
        int m = idx>>5, c = idx&31;
        float s0=0.f, sv=0.f;
        #pragma unroll
        for (int k=0;k<4;k++){
            float cc = c_C[k*4+m];
            s0 = fmaf(cc, W0[k*32+c], s0);
            sv = fmaf(cc, W2[k*32+c], sv);
        }
        g_a0[idx]=s0; g_aV[idx]=sv;
    }
    for (int idx=t; idx<14*16; idx+=stride) g_st0[idx]=0.0;
    for (int idx=t; idx<32*16; idx+=stride){ g_sum1[idx]=0.0; g_sq1[idx]=0.0; }
    for (int idx=t; idx<2*16;  idx+=stride) g_st2[idx]=0.0;
    for (int idx=t; idx<64*256; idx+=stride) g_h1raw[idx]=0.f;
}

__device__ __forceinline__ void smv_body(int i, const float* __restrict__ v,
                                         const int* __restrict__ src,
                                         const float* __restrict__ ew, float& acc){
    const int4*   sp = reinterpret_cast<const int4*>(src) + i*4;
    const float4* wp = reinterpret_cast<const float4*>(ew) + i*4;
    #pragma unroll
    for (int q=0;q<4;q++){
        int4 s = __ldg(sp+q); float4 w = __ldg(wp+q);
        acc = fmaf(w.x, __ldg(v+s.x), acc);
        acc = fmaf(w.y, __ldg(v+s.y), acc);
        acc = fmaf(w.z, __ldg(v+s.z), acc);
        acc = fmaf(w.w, __ldg(v+s.w), acc);
    }
}

__device__ __forceinline__ float gth16(const float* __restrict__ sbuf,
        const unsigned short* __restrict__ s16, const float* __restrict__ w, int n){
    float acc=0.f;
    const ushort4* sp = reinterpret_cast<const ushort4*>(s16) + n*4;
    const float4*  wp = reinterpret_cast<const float4*>(w) + n*4;
    #pragma unroll
    for (int q=0;q<4;q++){
        ushort4 s = sp[q]; float4 ww = __ldg(wp+q);
        acc = fmaf(ww.x, sbuf[s.x], acc);
        acc = fmaf(ww.y, sbuf[s.y], acc);
        acc = fmaf(ww.z, sbuf[s.z], acc);
        acc = fmaf(ww.w, sbuf[s.w], acc);
    }
    return acc;
}

// ---- layer 0: 2 chunks per graph, 1024 threads ----
__global__ void __launch_bounds__(1024) k_ls1(const float* __restrict__ x,
                                              const float* __restrict__ ew){
    __shared__ float sX[NEe];
    int g = blockIdx.x>>1, ch = blockIdx.x&1, tid = threadIdx.x;
    long nb = (long)g*NEe;
    for (int n=tid;n<NEe;n+=1024) sX[n] = __ldg(x+nb+n);
    __syncthreads();
    const unsigned short* s16 = g_u16a + nb*16;
    const float* w = ew + nb*16;
    int n1 = ch*CHK0+CHK0; if (n1>NEe) n1=NEe;
    for (int n=ch*CHK0+tid; n<n1; n+=1024)
        g_s1[nb+n] = gth16(sX, s16, w, n);
}
__global__ void __launch_bounds__(1024) k_ls2(const float* __restrict__ ew){
    __shared__ float sX[NEe];
    int g = blockIdx.x>>1, ch = blockIdx.x&1, tid = threadIdx.x;
    long nb = (long)g*NEe;
    for (int n=tid;n<NEe;n+=1024) sX[n] = g_s1[nb+n];
    __syncthreads();
    const unsigned short* s16 = g_u16a + nb*16;
    const float* w = ew + nb*16;
    int n1 = ch*CHK0+CHK0; if (n1>NEe) n1=NEe;
    for (int n=ch*CHK0+tid; n<n1; n+=1024)
        g_s2[nb+n] = gth16(sX, s16, w, n);
}
__global__ void __launch_bounds__(1024) k_ls3(const float* __restrict__ x,
                                              const float* __restrict__ ew){
    __shared__ float sX[NEe];
    __shared__ float shst[14];
    int g = blockIdx.x>>1, ch = blockIdx.x&1, tid = threadIdx.x;
    long nb = (long)g*NEe;
    if (tid<14) shst[tid]=0.f;
    for (int n=tid;n<NEe;n+=1024) sX[n] = g_s2[nb+n];
    __syncthreads();
    const unsigned short* s16 = g_u16a + nb*16;
    const float* w = ew + nb*16;
    int n1 = ch*CHK0+CHK0; if (n1>NEe) n1=NEe;
    float st[14];
    #pragma unroll
    for (int j=0;j<14;j++) st[j]=0.f;
    for (int n=ch*CHK0+tid; n<n1; n+=1024){
        float a = gth16(sX, s16, w, n);
        g_s3[nb+n]=a;
        float v0=__ldg(x+nb+n), v1=g_s1[nb+n], v2=sX[n], v3=a;
        st[0]+=v0; st[1]+=v1; st[2]+=v2; st[3]+=v3;
        st[4]+=v0*v0; st[5]+=v0*v1; st[6]+=v0*v2; st[7]+=v0*v3;
        st[8]+=v1*v1; st[9]+=v1*v2; st[10]+=v1*v3;
        st[11]+=v2*v2; st[12]+=v2*v3; st[13]+=v3*v3;
    }
    #pragma unroll
    for (int j=0;j<14;j++){
        #pragma unroll
        for (int r=16;r;r>>=1) st[j] += __shfl_xor_sync(0xffffffffu, st[j], r);
    }
    if ((tid&31)==0){
        #pragma unroll
        for (int j=0;j<14;j++) atomicAdd(&shst[j], st[j]);
    }
    __syncthreads();
    if (tid<14) atomicAdd(&g_st0[tid*16 + (blockIdx.x&15)], (double)shst[tid]);
}

__global__ void k_fin0(const float* __restrict__ b0, const float* __restrict__ g0,
                       const float* __restrict__ be0){
    int c = threadIdx.x; if (c>=32) return;
    double st[14];
    for (int j=0;j<14;j++){ double s=0; for (int q=0;q<16;q++) s+=g_st0[j*16+q]; st[j]=s; }
    double invN = 1.0/(double)NN1, mu[4];
    for (int m=0;m<4;m++) mu[m]=st[m]*invN;
    double cov[4][4]; int idx=4;
    for (int m=0;m<4;m++) for (int mm=m;mm<4;mm++){
        double cc = st[idx]*invN - mu[m]*mu[mm];
        cov[m][mm]=cc; cov[mm][m]=cc; idx++;
    }
    double a[4];
    for (int m=0;m<4;m++) a[m]=(double)g_a0[m*32+c];
    double proj=0, var=0;
    for (int m=0;m<4;m++) proj += mu[m]*a[m];
    for (int m=0;m<4;m++) for (int mm=0;mm<4;mm++) var += a[m]*a[mm]*cov[m][mm];
    double sc = (double)g0[c]/sqrt(var+1e-5);
    g_scale0[c]=(float)sc;
    g_shift0[c]=(float)((double)be0[c] - proj*sc);
}

// ---- fused pool + BN + mix GEMM: 64 nodes/block, 128 threads, 8x8 per thread ----
__global__ void __launch_bounds__(128) k_poolmix(const float* __restrict__ x){
    __shared__ float Xs[32*68];
    __shared__ float As[32*128];
    int tid=threadIdx.x, lane=tid&31, wid=tid>>5;
    for (int idx=tid; idx<4096; idx+=128){
        int k=idx>>7, col=idx&127, m=col>>5, c=col&31;
        As[idx] = g_A[m*1024 + k*32 + c];
    }
    float a0=g_a0[lane], a1=g_a0[32+lane], a2=g_a0[64+lane], a3=g_a0[96+lane];
    float sc=g_scale0[lane], sf=g_shift0[lane];
    int nbase = blockIdx.x*64;
    #pragma unroll
    for (int j=0;j<16;j++){
        int nl = wid*16+j, n = nbase+nl;
        int b = n/NE2e, e2 = n-b*NE2e; int m0 = b*NEe + 2*e2;
        float s0a=__ldg(x+m0),   s1a=g_s1[m0],   s2a=g_s2[m0],   s3a=g_s3[m0];
        float s0b=__ldg(x+m0+1), s1b=g_s1[m0+1], s2b=g_s2[m0+1], s3b=g_s3[m0+1];
        float ra = fmaf(s0a,a0, fmaf(s1a,a1, fmaf(s2a,a2, s3a*a3)));
        float rb = fmaf(s0b,a0, fmaf(s1b,a1, fmaf(s2b,a2, s3b*a3)));
        Xs[lane*68 + nl] = fmaxf(leaky(fmaf(ra,sc,sf)), leaky(fmaf(rb,sc,sf)));
    }
    __syncthreads();
    int tr = tid&7, tc = tid>>3;        // rows 8*tr..+7, cols 8*tc..+7
    float acc[8][8];
    #pragma unroll
    for (int r=0;r<8;r++)
        #pragma unroll
        for (int c=0;c<8;c++) acc[r][c]=0.f;
    #pragma unroll 2
    for (int k=0;k<32;k++){
        float4 xr0 = *reinterpret_cast<float4*>(&Xs[k*68 + 8*tr]);
        float4 xr1 = *reinterpret_cast<float4*>(&Xs[k*68 + 8*tr + 4]);
        float4 av0 = *reinterpret_cast<float4*>(&As[k*128 + 8*tc]);
        float4 av1 = *reinterpret_cast<float4*>(&As[k*128 + 8*tc + 4]);
        float xv[8] = {xr0.x,xr0.y,xr0.z,xr0.w, xr1.x,xr1.y,xr1.z,xr1.w};
        float av[8] = {av0.x,av0.y,av0.z,av0.w, av1.x,av1.y,av1.z,av1.w};
        #pragma unroll
        for (int r=0;r<8;r++)
            #pragma unroll
            for (int c=0;c<8;c++) acc[r][c] = fmaf(xv[r], av[c], acc[r][c]);
    }
    int m = tc>>2, cc = (tc&3)*8;
    float* Yp = g_Y + (size_t)m*YSZ;
    #pragma unroll
    for (int r=0;r<8;r++){
        size_t base = (size_t)(nbase + 8*tr + r)*32 + cc;
        *reinterpret_cast<float4*>(&Yp[base])   = make_float4(acc[r][0],acc[r][1],acc[r][2],acc[r][3]);
        *reinterpret_cast<float4*>(&Yp[base+4]) = make_float4(acc[r][4],acc[r][5],acc[r][6],acc[r][7]);
    }
}

// ---- 32-ch matvec: 2 nodes per warp ----
__global__ void __launch_bounds__(256) k_mvA(const int* __restrict__ src,
                                             const float* __restrict__ ew){
    __shared__ int ss[8][32]; __shared__ float sw[8][32];
    int tid=threadIdx.x, lane=tid&31, wid=tid>>5;
    int n0 = blockIdx.x*16 + wid*2;
    ss[wid][lane]=src[n0*16+lane]; sw[wid][lane]=ew[n0*16+lane];
    __syncwarp();
    const float* v = g_Y + 3*YSZ;
    float acc0 = g_Y[2*YSZ + (size_t)n0*32+lane];
    float acc1 = g_Y[2*YSZ + (size_t)(n0+1)*32+lane];
    #pragma unroll
    for (int j=0;j<16;j++){
        acc0 = fmaf(sw[wid][j],    __ldg(v + (size_t)ss[wid][j]*32 + lane), acc0);
        acc1 = fmaf(sw[wid][16+j], __ldg(v + (size_t)ss[wid][16+j]*32 + lane), acc1);
    }
    g_R1[(size_t)n0*32+lane]=acc0;
    g_R1[(size_t)(n0+1)*32+lane]=acc1;
}
__global__ void __launch_bounds__(256) k_mvB(const int* __restrict__ src,
                                             const float* __restrict__ ew){
    __shared__ int ss[8][32]; __shared__ float sw[8][32];
    int tid=threadIdx.x, lane=tid&31, wid=tid>>5;
    int n0 = blockIdx.x*16 + wid*2;
    ss[wid][lane]=src[n0*16+lane]; sw[wid][lane]=ew[n0*16+lane];
    __syncwarp();
    float acc0 = g_Y[YSZ + (size_t)n0*32+lane];
    float acc1 = g_Y[YSZ + (size_t)(n0+1)*32+lane];
    #pragma unroll
    for (int j=0;j<16;j++){
        acc0 = fmaf(sw[wid][j],    __ldg(g_R1 + (size_t)ss[wid][j]*32 + lane), acc0);
        acc1 = fmaf(sw[wid][16+j], __ldg(g_R1 + (size_t)ss[wid][16+j]*32 + lane), acc1);
    }
    g_R2[(size_t)n0*32+lane]=acc0;
    g_R2[(size_t)(n0+1)*32+lane]=acc1;
}

__global__ void __launch_bounds__(256) k_mvC(const int* __restrict__ src,
        const float* __restrict__ ew, const float* __restrict__ b1){
    __shared__ int   ss[8][16];
    __shared__ float sw[8][16];
    __shared__ float sum_s[32], sq_s[32];
    int tid=threadIdx.x, lane=tid&31, wid=tid>>5;
    if (tid<32){ sum_s[tid]=0.f; sq_s[tid]=0.f; }
    __syncthreads();
    float bias = __ldg(b1+lane);
    int w0 = blockIdx.x*8 + wid, nw = gridDim.x*8;
    float ps=0.f, pq=0.f;
    for (int n=w0; n<NN2; n+=nw){
        if (lane<16) ss[wid][lane] = src[n*16+lane];
        else         sw[wid][lane-16] = ew[n*16+lane-16];
        __syncwarp();
        float acc = g_Y[(size_t)n*32+lane] + bias;
        #pragma unroll
        for (int j=0;j<16;j++)
            acc = fmaf(sw[wid][j], __ldg(g_R2 + (size_t)ss[wid][j]*32 + lane), acc);
        g_O1[(size_t)n*32+lane] = acc;
        ps += acc; pq += acc*acc;
        __syncwarp();
    }
    atomicAdd(&sum_s[lane], ps); atomicAdd(&sq_s[lane], pq);
    __syncthreads();
    if (tid<32){
        int slot = blockIdx.x&15;
        atomicAdd(&g_sum1[tid*16+slot], (double)sum_s[tid]);
        atomicAdd(&g_sq1[tid*16+slot],  (double)sq_s[tid]);
    }
}

__global__ void k_fin1(const float* __restrict__ g1, const float* __restrict__ be1){
    int c=threadIdx.x; if (c>=32) return;
    double s=0,q=0;
    for (int slot=0;slot<16;slot++){ s+=g_sum1[c*16+slot]; q+=g_sq1[c*16+slot]; }
    double invN = 1.0/(double)NN2;
    double mean=s*invN, var=q*invN-mean*mean;
    double sc=(double)g1[c]/sqrt(var+1e-5);
    g_scale1[c]=(float)sc; g_shift1[c]=(float)((double)be1[c]-mean*sc);
}

__global__ void k_mix2(){
    int w=(blockIdx.x*blockDim.x+threadIdx.x)>>5; if (w>=NN2) return;
    int lane=threadIdx.x&31;
    float o=g_O1[(size_t)w*32+lane];
    float x2=leaky(fmaf(g_scale1[lane], o, g_shift1[lane]));
    float p0=x2*g_aV[lane],     p1=x2*g_aV[32+lane];
    float p2=x2*g_aV[64+lane],  p3=x2*g_aV[96+lane];
    #pragma unroll
    for (int r=16;r;r>>=1){
        p0+=__shfl_xor_sync(0xffffffffu,p0,r); p1+=__shfl_xor_sync(0xffffffffu,p1,r);
        p2+=__shfl_xor_sync(0xffffffffu,p2,r); p3+=__shfl_xor_sync(0xffffffffu,p3,r);
    }
    if (lane==0){ g_w0[w]=p0; g_w1[w]=p1; g_w2[w]=p2; g_w3[w]=p3; }
}

__global__ void k_sc1(const int* __restrict__ src, const float* __restrict__ ew){
    int i = blockIdx.x*blockDim.x+threadIdx.x; if (i>=NN2) return;
    float a=g_w2[i]; smv_body(i, g_w3, src, ew, a); g_r1[i]=a;
}
__global__ void k_sc2(const int* __restrict__ src, const float* __restrict__ ew){
    int i = blockIdx.x*blockDim.x+threadIdx.x; if (i>=NN2) return;
    float a=g_w1[i]; smv_body(i, g_r1, src, ew, a); g_r2[i]=a;
}
__global__ void k_sc3(const int* __restrict__ src, const float* __restrict__ ew,
                      const float* __restrict__ b2){
    int stride = gridDim.x*blockDim.x;
    float bias=__ldg(b2);
    float ps=0.f,pq=0.f;
    for (int i = blockIdx.x*blockDim.x+threadIdx.x; i<NN2; i+=stride){
        float a=g_w0[i]+bias; smv_body(i, g_r2, src, ew, a);
        g_raw2[i]=a; ps+=a; pq+=a*a;
    }
    __shared__ float sh[2];
    if (threadIdx.x<2) sh[threadIdx.x]=0.f;
    __syncthreads();
    #pragma unroll
    for (int r=16;r;r>>=1){ ps+=__shfl_xor_sync(0xffffffffu,ps,r); pq+=__shfl_xor_sync(0xffffffffu,pq,r); }
    if ((threadIdx.x&31)==0){ atomicAdd(&sh[0],ps); atomicAdd(&sh[1],pq); }
    __syncthreads();
    if (threadIdx.x<2)
        atomicAdd(&g_st2[threadIdx.x*16 + (blockIdx.x&15)], (double)sh[threadIdx.x]);
}

__global__ void k_finS(const float* __restrict__ g2, const float* __restrict__ be2){
    if (threadIdx.x!=0) return;
    double s=0,q=0;
    for (int slot=0;slot<16;slot++){ s+=g_st2[slot]; q+=g_st2[16+slot]; }
    double invN=1.0/(double)NN2;
    double mean=s*invN, var=q*invN-mean*mean;
    double sc=(double)g2[0]/sqrt(var+1e-5);
    g_bn2s[0]=(float)sc; g_bn2s[1]=(float)((double)be2[0]-mean*sc);
}

__global__ void __launch_bounds__(256) k_mlp1(const float* __restrict__ W,
                                              const float* __restrict__ bb){
    extern __shared__ float sA[];
    int tid = threadIdx.x;
    int cb = blockIdx.x & 7, kc = blockIdx.x >> 3;
    int k0 = kc*MCHK;
    int klen = NE2e - k0; if (klen > MCHK) klen = MCHK;
    float sc = g_bn2s[0], sf = g_bn2s[1];
    for (int idx=tid; idx<64*klen; idx+=256){
        int r = idx / klen, k = idx - r*klen;
        sA[r*MCHK + k] = leaky(fmaf(g_raw2[(long)r*NE2e + k0 + k], sc, sf));
    }
    __syncthreads();
    int col = cb*32 + (tid&31);
    int r0 = (tid>>5)*8;
    float acc[8];
    #pragma unroll
    for (int r=0;r<8;r++) acc[r]=0.f;
    for (int k=0;k<klen;k++){
        float wv = __ldg(W + (long)(k0+k)*256 + col);
        #pragma unroll
        for (int r=0;r<8;r++) acc[r] = fmaf(sA[(r0+r)*MCHK + k], wv, acc[r]);
    }
    float bias = (kc==0) ? __ldg(bb+col) : 0.f;
    #pragma unroll
    for (int r=0;r<8;r++) atomicAdd(&g_h1raw[(r0+r)*256 + col], acc[r] + bias);
}

__global__ void k_bn1(const float* __restrict__ g, const float* __restrict__ be){
    int c=threadIdx.x;
    float s=0.f,q=0.f;
    #pragma unroll 8
    for (int b=0;b<64;b++){ float v=g_h1raw[b*256+c]; s+=v; q+=v*v; }
    float mean=s*(1.f/64.f), var=q*(1.f/64.f)-mean*mean;
    float sc=__ldg(g+c)*rsqrtf(var+1e-5f), sf=__ldg(be+c)-mean*sc;
    for (int b=0;b<64;b++){
        float v=fmaf(g_h1raw[b*256+c],sc,sf);
        g_h1[b*256+c]= v>0.f? v:0.f;
    }
}

__global__ void k_mlp2(const float* __restrict__ W, const float* __restrict__ bb){
    __shared__ float shx[256];
    int b = blockIdx.x, t = threadIdx.x;
    for (int i=t;i<256;i+=128) shx[i]=g_h1[b*256+i];
    __syncthreads();
    float acc=__ldg(bb+t);
    #pragma unroll 8
    for (int i=0;i<256;i++) acc = fmaf(shx[i], __ldg(W+i*128+t), acc);
    g_h2raw[b*128+t]=acc;
}

__global__ void k_bn2out(const float* __restrict__ g, const float* __restrict__ be,
                         const float* __restrict__ W3, const float* __restrict__ b3,
                         float* __restrict__ out){
    __shared__ float sh2[64*128];
    int c=threadIdx.x;
    float s=0.f,q=0.f;
    #pragma unroll 8
    for (int b=0;b<64;b++){ float v=g_h2raw[b*128+c]; s+=v; q+=v*v; }
    float mean=s*(1.f/64.f), var=q*(1.f/64.f)-mean*mean;
    float sc=__ldg(g+c)*rsqrtf(var+1e-5f), sf=__ldg(be+c)-mean*sc;
    for (int b=0;b<64;b++){
        float v=fmaf(g_h2raw[b*128+c],sc,sf);
        sh2[b*128+c]= v>0.f? v:0.f;
    }
    __syncthreads();
    if (c<64){
        float acc=__ldg(b3);
        #pragma unroll 8
        for (int j=0;j<128;j++) acc=fmaf(sh2[c*128+j], __ldg(W3+j), acc);
        out[c]=acc;
    }
}

extern "C" void kernel_launch(void* const* d_in, const int* in_sizes, int n_in,
                              void* d_out, int out_size){
    const float* x_s  = (const float*)d_in[0];
    const int*   ei1  = (const int*)d_in[1];
    const float* ew1  = (const float*)d_in[2];
    const int*   ei2  = (const int*)d_in[3];
    const float* ew2  = (const float*)d_in[4];
    const float* W0   = (const float*)d_in[5];
    const float* b0   = (const float*)d_in[6];
    const float* g0   = (const float*)d_in[7];
    const float* be0  = (const float*)d_in[8];
    const float* W1   = (const float*)d_in[9];
    const float* b1   = (const float*)d_in[10];
    const float* g1   = (const float*)d_in[11];
    const float* be1  = (const float*)d_in[12];
    const float* W2   = (const float*)d_in[13];
    const float* b2   = (const float*)d_in[14];
    const float* g2   = (const float*)d_in[15];
    const float* be2  = (const float*)d_in[16];
    const float* l1W  = (const float*)d_in[17];
    const float* l1b  = (const float*)d_in[18];
    const float* bn1g = (const float*)d_in[19];
    const float* bn1b = (const float*)d_in[20];
    const float* l2W  = (const float*)d_in[21];
    const float* l2b  = (const float*)d_in[22];
    const float* bn2g = (const float*)d_in[23];
    const float* bn2b = (const float*)d_in[24];
    const float* l3W  = (const float*)d_in[25];
    const float* l3b  = (const float*)d_in[26];
    float* out = (float*)d_out;

    const int smM1 = 64*MCHK*(int)sizeof(float);
    static int init = 0;
    if (!init){
        cudaFuncSetAttribute(k_mlp1, cudaFuncAttributeMaxDynamicSharedMemorySize, smM1);
        init = 1;
    }

    k_prep<<<256,256>>>(W0, W1, W2, ei1);
    k_ls1<<<128,1024>>>(x_s, ew1);
    k_ls2<<<128,1024>>>(ew1);
    k_ls3<<<128,1024>>>(x_s, ew1);
    k_fin0<<<1,32>>>(b0, g0, be0);
    k_poolmix<<<NN2/64,128>>>(x_s);
    k_mvA<<<NN2/16,256>>>(ei2, ew2);
    k_mvB<<<NN2/16,256>>>(ei2, ew2);
    k_mvC<<<GSB,256>>>(ei2, ew2, b1);
    k_fin1<<<1,32>>>(g1, be1);
    k_mix2<<<(NN2*32+255)/256,256>>>();
    int nb2 = (NN2+255)/256;
    k_sc1<<<nb2,256>>>(ei2, ew2);
    k_sc2<<<nb2,256>>>(ei2, ew2);
    k_sc3<<<GSB,256>>>(ei2, ew2, b2);
    k_finS<<<1,32>>>(g2, be2);
    k_mlp1<<<64,256,smM1>>>(l1W, l1b);
    k_bn1<<<1,256>>>(bn1g, bn1b);
    k_mlp2<<<64,128>>>(l2W, l2b);
    k_bn2out<<<1,128>>>(bn2g, bn2b, l3W, l3b, out);
}